// round 12
// baseline (speedup 1.0000x reference)
#include <cuda_runtime.h>
#include <cuda_bf16.h>
#include <mma.h>
#include <math.h>
#include <cstdint>
#include <stdint.h>

using namespace nvcuda;

// Problem constants
#define Lc 15
#define Dc 512
#define Hc 64
#define HDc 8
#define Fc 2048
#define Gc 128
#define Bc 4
#define Nc 256
#define Mc (Bc*Nc)   // 1024 rows
#define SPLITK 4
#define TABN 8192

// -------- scratch (device globals; no allocation allowed) --------
__device__ float g_h[Mc*Dc];
__device__ float g_x[Mc*Dc];
__device__ float g_qkv[Mc*3*Dc];
__device__ float g_attn[Mc*Dc];
__device__ float g_ffn[Mc*Fc];
__device__ float g_pair[Bc*Nc*Nc];
__device__ float g_split[SPLITK*Mc*Dc];
__device__ float g_tab[TABN+1];

// RNE round fp32 -> tf32 (value stays in fp32 container)
__device__ __forceinline__ float tf32r(float x) {
    float y;
    asm("cvt.rna.tf32.f32 %0, %1;" : "=f"(y) : "f"(x));
    return y;
}

// ---------------- gaussian table build ----------------
__global__ void tab_kernel(const float* __restrict__ mu,
                           const float* __restrict__ sigma,
                           const float* __restrict__ plw,
                           const float* __restrict__ plb) {
    int i = blockIdx.x*256 + threadIdx.x;
    if (i > TABN) return;
    float da = -8.0f + (float)i * (1.0f/512.0f);
    float s = 0.f;
    #pragma unroll 8
    for (int g = 0; g < Gc; g++) {
        float sg = sigma[g];
        float coef = plw[g] / (2.0f*sg*sg) / (sg * 2.5066282746310002f);
        float t = da - mu[g];
        s += __expf(-t*t) * coef;
    }
    g_tab[i] = s + plb[0];
}

// ---------------- pair representation via table lookup ----------------
__global__ void pair_kernel(const float* __restrict__ coords,
                            const int* __restrict__ ptypes,
                            const float* __restrict__ pa,
                            const float* __restrict__ pb,
                            float* __restrict__ pr) {
    int p = blockIdx.x * blockDim.x + threadIdx.x;
    int b = p >> 16;
    int rem = p & 65535;
    int i = rem >> 8, j = rem & 255;
    const float* ci = coords + (b*Nc + i)*3;
    const float* cj = coords + (b*Nc + j)*3;
    float dx = ci[0]-cj[0], dy = ci[1]-cj[1], dz = ci[2]-cj[2];
    float d2 = dx*dx + dy*dy + dz*dz;
    float dist = sqrtf(fmaxf(d2, 1e-12f));
    int pt = ptypes[p];
    float da = pa[pt]*dist + pb[pt];
    float t = (da + 8.0f) * 512.0f;
    t = fminf(fmaxf(t, 0.0f), (float)(TABN - 1));
    int idx = (int)t;
    float fr = t - (float)idx;
    float f0 = g_tab[idx], f1 = g_tab[idx+1];
    pr[p] = f0 + fr*(f1 - f0);
}

// ---------------- embedding ----------------
__global__ void emb_kernel(const int* __restrict__ atom_types,
                           const float* __restrict__ atom_emb,
                           float* __restrict__ h) {
    int idx = blockIdx.x * blockDim.x + threadIdx.x;
    if (idx >= Mc*Dc) return;
    int row = idx >> 9;
    int d   = idx & 511;
    h[idx] = atom_emb[atom_types[row]*Dc + d];
}

// ---------------- layernorm (emits tf32-rounded fp32) ----------------
__global__ __launch_bounds__(128) void ln_kernel(const float* __restrict__ in,
                                                 const float* __restrict__ g,
                                                 const float* __restrict__ bb,
                                                 float* __restrict__ out) {
    int row = blockIdx.x;
    int tid = threadIdx.x;
    const float* x = in + row*Dc;
    float v[4], s = 0.f, s2 = 0.f;
    #pragma unroll
    for (int j = 0; j < 4; j++) {
        v[j] = x[tid + 128*j];
        s += v[j]; s2 += v[j]*v[j];
    }
    #pragma unroll
    for (int off = 16; off; off >>= 1) {
        s  += __shfl_xor_sync(0xffffffff, s,  off);
        s2 += __shfl_xor_sync(0xffffffff, s2, off);
    }
    __shared__ float rs[4], rs2[4];
    int wid = tid >> 5, lane = tid & 31;
    if (lane == 0) { rs[wid] = s; rs2[wid] = s2; }
    __syncthreads();
    s  = rs[0]+rs[1]+rs[2]+rs[3];
    s2 = rs2[0]+rs2[1]+rs2[2]+rs2[3];
    float mean = s * (1.0f/Dc);
    float var  = s2 * (1.0f/Dc) - mean*mean;
    float rstd = rsqrtf(var + 1e-5f);
    #pragma unroll
    for (int j = 0; j < 4; j++) {
        int d = tid + 128*j;
        out[row*Dc + d] = tf32r((v[j]-mean)*rstd*g[d] + bb[d]);
    }
}

// ---------------- fused split-K reduce + layernorm ----------------
// h stays full fp32; x output tf32-rounded
__global__ __launch_bounds__(128) void reduce_ln_kernel(
    const float* __restrict__ P, const float* __restrict__ bias,
    float* __restrict__ h, const float* __restrict__ g,
    const float* __restrict__ bb, float* __restrict__ xout) {
    int row = blockIdx.x;
    int tid = threadIdx.x;
    const int MN = Mc*Dc;
    float v[4], s = 0.f, s2 = 0.f;
    #pragma unroll
    for (int j = 0; j < 4; j++) {
        int d = tid + 128*j;
        int idx = row*Dc + d;
        float val = h[idx] + bias[d]
                  + P[idx] + P[idx + MN] + P[idx + 2*MN] + P[idx + 3*MN];
        h[idx] = val;
        v[j] = val; s += val; s2 += val*val;
    }
    #pragma unroll
    for (int off = 16; off; off >>= 1) {
        s  += __shfl_xor_sync(0xffffffff, s,  off);
        s2 += __shfl_xor_sync(0xffffffff, s2, off);
    }
    __shared__ float rs[4], rs2[4];
    int wid = tid >> 5, lane = tid & 31;
    if (lane == 0) { rs[wid] = s; rs2[wid] = s2; }
    __syncthreads();
    s  = rs[0]+rs[1]+rs[2]+rs[3];
    s2 = rs2[0]+rs2[1]+rs2[2]+rs2[3];
    float mean = s * (1.0f/Dc);
    float var  = s2 * (1.0f/Dc) - mean*mean;
    float rstd = rsqrtf(var + 1e-5f);
    #pragma unroll
    for (int j = 0; j < 4; j++) {
        int d = tid + 128*j;
        xout[row*Dc + d] = tf32r((v[j]-mean)*rstd*g[d] + bb[d]);
    }
}

// ---------------- plain split-K reduce (final layer) ----------------
__global__ __launch_bounds__(256) void reduce_splitk(const float* __restrict__ P,
                                                     const float* __restrict__ bias,
                                                     float* __restrict__ h,
                                                     int MN, int N) {
    int i4 = blockIdx.x*256 + threadIdx.x;
    if (i4 >= MN/4) return;
    int n = (i4*4) & (N-1);
    const float4* P4 = (const float4*)P;
    int stride4 = MN/4;
    float4 s0 = P4[i4];
    float4 s1 = P4[i4 + stride4];
    float4 s2 = P4[i4 + 2*stride4];
    float4 s3 = P4[i4 + 3*stride4];
    float4 b  = *(const float4*)(bias + n);
    float4 hv = ((float4*)h)[i4];
    hv.x += s0.x + s1.x + s2.x + s3.x + b.x;
    hv.y += s0.y + s1.y + s2.y + s3.y + b.y;
    hv.z += s0.z + s1.z + s2.z + s3.z + b.z;
    hv.w += s0.w + s1.w + s2.w + s3.w + b.w;
    ((float4*)h)[i4] = hv;
}

// ---------------- tf32 tensor-core GEMM, double-buffered, 1 sync/tile ----------------
// C = act(A @ W^T + bias); A pre-rounded to tf32 by producers, W rounded at staging.
// gridDim.z>1: K sliced, raw partials to C + z*M*N (no epilogue).
#define BM 128
#define BN 64
#define BKT 32
#define LDAF 36              // fp32 leading dim (floats)
#define LDC 68
#define SBUF 27648           // (128+64)*36*4 bytes per stage
#define SMEM_DYN (2*SBUF)    // 55296
__global__ __launch_bounds__(256, 2) void gemm_tf32_kernel(
    const float* __restrict__ A, const float* __restrict__ W,
    const float* __restrict__ bias, const float* __restrict__ res,
    float* __restrict__ C, int M, int N, int K, int act)
{
    extern __shared__ __align__(16) char smem[];
    int tid = threadIdx.x;
    int m0 = blockIdx.y*BM, n0 = blockIdx.x*BN;
    int S = gridDim.z;
    int Ks = K / S;
    int kbeg = blockIdx.z * Ks;

    int wid = tid >> 5;
    int wm = (wid >> 1) * 32;
    int wn = (wid & 1) * 32;

    wmma::fragment<wmma::accumulator, 16, 16, 8, float> acc[2][2];
    #pragma unroll
    for (int i = 0; i < 2; i++)
        #pragma unroll
        for (int j = 0; j < 2; j++)
            wmma::fill_fragment(acc[i][j], 0.0f);

    // prefetch tile 0: A 128x32 fp32 (4 float4/thread), W 64x32 (2 float4/thread)
    float4 ra[4], rw[2];
    #pragma unroll
    for (int i = 0; i < 4; i++) {
        int idx = tid + i*256, row = idx >> 3, c = (idx & 7)*4;
        ra[i] = *(const float4*)(A + (size_t)(m0+row)*K + kbeg + c);
    }
    #pragma unroll
    for (int i = 0; i < 2; i++) {
        int idx = tid + i*256, row = idx >> 3, c = (idx & 7)*4;
        rw[i] = *(const float4*)(W + (size_t)(n0+row)*K + kbeg + c);
    }

    int nt = Ks / BKT;
    for (int t = 0; t < nt; t++) {
        float* Af = (float*)(smem + (t & 1)*SBUF);
        float* Wf = Af + BM*LDAF;

        #pragma unroll
        for (int i = 0; i < 4; i++) {
            int idx = tid + i*256, row = idx >> 3, c = (idx & 7)*4;
            *(float4*)&Af[row*LDAF + c] = ra[i];   // A pre-rounded by producers
        }
        #pragma unroll
        for (int i = 0; i < 2; i++) {
            int idx = tid + i*256, row = idx >> 3, c = (idx & 7)*4;
            float4 v = rw[i];
            v.x = tf32r(v.x); v.y = tf32r(v.y);
            v.z = tf32r(v.z); v.w = tf32r(v.w);
            *(float4*)&Wf[row*LDAF + c] = v;
        }

        if (t + 1 < nt) {
            int k0 = (t+1)*BKT;
            #pragma unroll
            for (int i = 0; i < 4; i++) {
                int idx = tid + i*256, row = idx >> 3, c = (idx & 7)*4;
                ra[i] = *(const float4*)(A + (size_t)(m0+row)*K + kbeg + k0 + c);
            }
            #pragma unroll
            for (int i = 0; i < 2; i++) {
                int idx = tid + i*256, row = idx >> 3, c = (idx & 7)*4;
                rw[i] = *(const float4*)(W + (size_t)(n0+row)*K + kbeg + k0 + c);
            }
        }

        __syncthreads();   // the ONLY barrier per tile

        #pragma unroll
        for (int ks = 0; ks < BKT; ks += 8) {
            wmma::fragment<wmma::matrix_a, 16, 16, 8, wmma::precision::tf32, wmma::row_major> af[2];
            wmma::fragment<wmma::matrix_b, 16, 16, 8, wmma::precision::tf32, wmma::col_major> bf[2];
            #pragma unroll
            for (int i = 0; i < 2; i++)
                wmma::load_matrix_sync(af[i], Af + (wm + i*16)*LDAF + ks, LDAF);
            #pragma unroll
            for (int j = 0; j < 2; j++)
                wmma::load_matrix_sync(bf[j], Wf + (wn + j*16)*LDAF + ks, LDAF);
            #pragma unroll
            for (int i = 0; i < 2; i++)
                #pragma unroll
                for (int j = 0; j < 2; j++)
                    wmma::mma_sync(acc[i][j], af[i], bf[j], acc[i][j]);
        }
        // no trailing sync: next iteration writes the other buffer
    }

    if (S > 1) {
        float* Cp = C + (size_t)blockIdx.z*M*N;
        #pragma unroll
        for (int i = 0; i < 2; i++)
            #pragma unroll
            for (int j = 0; j < 2; j++)
                wmma::store_matrix_sync(Cp + (size_t)(m0+wm+i*16)*N + n0+wn+j*16,
                                        acc[i][j], N, wmma::mem_row_major);
        return;
    }

    __syncthreads();
    float* Ct = (float*)smem;
    #pragma unroll
    for (int i = 0; i < 2; i++)
        #pragma unroll
        for (int j = 0; j < 2; j++)
            wmma::store_matrix_sync(Ct + (wm+i*16)*LDC + wn+j*16,
                                    acc[i][j], LDC, wmma::mem_row_major);
    __syncthreads();

    int col = (tid & 15) * 4;
    int r0  = tid >> 4;
    float4 bv = make_float4(0.f, 0.f, 0.f, 0.f);
    if (bias) bv = *(const float4*)(bias + n0 + col);
    #pragma unroll
    for (int rr = 0; rr < 8; rr++) {
        int row = rr*16 + r0;
        float vr[4];
        *(float4*)vr = *(const float4*)&Ct[row*LDC + col];
        vr[0] += bv.x; vr[1] += bv.y; vr[2] += bv.z; vr[3] += bv.w;
        if (act == 1) {
            #pragma unroll
            for (int j = 0; j < 4; j++)
                vr[j] = tf32r(0.5f * vr[j] * (1.0f + erff(vr[j] * 0.7071067811865475f)));
        }
        float* dst = C + (size_t)(m0+row)*N + n0 + col;
        if (res) {
            float4 r = *(const float4*)(res + (size_t)(m0+row)*N + n0 + col);
            vr[0]+=r.x; vr[1]+=r.y; vr[2]+=r.z; vr[3]+=r.w;
        }
        *(float4*)dst = *(float4*)vr;
    }
}

// ---------------- fused attention (QKV bias + scores + softmax + PV) ----------------
// output tf32-rounded for the out-proj GEMM
__global__ __launch_bounds__(256) void attn_kernel(const float* __restrict__ qkv,
                                                   const float* __restrict__ qb,
                                                   const float* __restrict__ pr,
                                                   const float* __restrict__ ppw,
                                                   const float* __restrict__ ppb,
                                                   float* __restrict__ out) {
    int b = blockIdx.x >> 6;
    int h = blockIdx.x & 63;
    __shared__ float Ks[Nc*9];
    __shared__ float Vs[Nc*9];
    int tid = threadIdx.x;
    float4 bq0 = *(const float4*)(qb + h*HDc);
    float4 bq1 = *(const float4*)(qb + h*HDc + 4);
    float4 bk0 = *(const float4*)(qb + Dc + h*HDc);
    float4 bk1 = *(const float4*)(qb + Dc + h*HDc + 4);
    float4 bv0 = *(const float4*)(qb + 2*Dc + h*HDc);
    float4 bv1 = *(const float4*)(qb + 2*Dc + h*HDc + 4);
    {
        int n = tid;
        const float* kp = qkv + (((b*Nc + n)*3 + 1))*Dc + h*HDc;
        const float* vp = kp + Dc;
        float4 k0 = *(const float4*)kp,     k1 = *(const float4*)(kp+4);
        float4 v0 = *(const float4*)vp,     v1 = *(const float4*)(vp+4);
        float* kd = &Ks[n*9];
        kd[0]=k0.x+bk0.x; kd[1]=k0.y+bk0.y; kd[2]=k0.z+bk0.z; kd[3]=k0.w+bk0.w;
        kd[4]=k1.x+bk1.x; kd[5]=k1.y+bk1.y; kd[6]=k1.z+bk1.z; kd[7]=k1.w+bk1.w;
        float* vd = &Vs[n*9];
        vd[0]=v0.x+bv0.x; vd[1]=v0.y+bv0.y; vd[2]=v0.z+bv0.z; vd[3]=v0.w+bv0.w;
        vd[4]=v1.x+bv1.x; vd[5]=v1.y+bv1.y; vd[6]=v1.z+bv1.z; vd[7]=v1.w+bv1.w;
    }
    __syncthreads();
    const float scale = 0.3535533905932738f;
    float pw = ppw[h], pb = ppb[h];
    int warp = tid >> 5, lane = tid & 31;
    #pragma unroll
    for (int r = 0; r < 8; r++) {
        int i = blockIdx.y*64 + warp*8 + r;
        const float* qp = qkv + ((b*Nc + i)*3)*Dc + h*HDc;
        float4 q0 = *(const float4*)qp, q1 = *(const float4*)(qp+4);
        float qr[8];
        qr[0]=q0.x+bq0.x; qr[1]=q0.y+bq0.y; qr[2]=q0.z+bq0.z; qr[3]=q0.w+bq0.w;
        qr[4]=q1.x+bq1.x; qr[5]=q1.y+bq1.y; qr[6]=q1.z+bq1.z; qr[7]=q1.w+bq1.w;
        const float* prow = pr + (b*Nc + i)*Nc;
        float s[8];
        float mx = -1e30f;
        #pragma unroll
        for (int jj = 0; jj < 8; jj++) {
            int j = lane + 32*jj;
            const float* kk = &Ks[j*9];
            float d = qr[0]*kk[0] + qr[1]*kk[1] + qr[2]*kk[2] + qr[3]*kk[3]
                    + qr[4]*kk[4] + qr[5]*kk[5] + qr[6]*kk[6] + qr[7]*kk[7];
            s[jj] = d*scale + prow[j]*pw + pb;
            mx = fmaxf(mx, s[jj]);
        }
        #pragma unroll
        for (int off = 16; off; off >>= 1)
            mx = fmaxf(mx, __shfl_xor_sync(0xffffffff, mx, off));
        float sum = 0.f;
        #pragma unroll
        for (int jj = 0; jj < 8; jj++) { s[jj] = __expf(s[jj]-mx); sum += s[jj]; }
        #pragma unroll
        for (int off = 16; off; off >>= 1)
            sum += __shfl_xor_sync(0xffffffff, sum, off);
        float inv = 1.0f / sum;
        float acc[8] = {};
        #pragma unroll
        for (int jj = 0; jj < 8; jj++) {
            int j = lane + 32*jj;
            float p = s[jj]*inv;
            const float* vv = &Vs[j*9];
            #pragma unroll
            for (int d = 0; d < 8; d++) acc[d] += p*vv[d];
        }
        #pragma unroll
        for (int off = 16; off; off >>= 1) {
            #pragma unroll
            for (int d = 0; d < 8; d++)
                acc[d] += __shfl_xor_sync(0xffffffff, acc[d], off);
        }
        if (lane == 0) {
            float* op = out + (b*Nc + i)*Dc + h*HDc;
            #pragma unroll
            for (int d = 0; d < 8; d++) op[d] = tf32r(acc[d]);
        }
    }
}

// ---------------- SE(3) coordinate update ----------------
__global__ __launch_bounds__(128) void coords_kernel(const float* __restrict__ coords,
                                                     const float* __restrict__ pr,
                                                     const float* __restrict__ uw,
                                                     const float* __restrict__ ub,
                                                     const float* __restrict__ ww,
                                                     const float* __restrict__ wb,
                                                     float* __restrict__ out) {
    int gw = blockIdx.x * 4 + (threadIdx.x >> 5);
    int lane = threadIdx.x & 31;
    int b = gw >> 8, i = gw & 255;
    float u0 = uw[0], u1 = ub[0], w0 = ww[0], w1 = wb[0];
    const float* ci = coords + (b*Nc + i)*3;
    float cx = ci[0], cy = ci[1], cz = ci[2];
    float ax = 0.f, ay = 0.f, az = 0.f;
    const float* prow = pr + (b*Nc + i)*Nc;
    #pragma unroll
    for (int jj = 0; jj < 8; jj++) {
        int j = lane + 32*jj;
        const float* cj = coords + (b*Nc + j)*3;
        float c = (fmaxf(prow[j], 0.f)*u0 + u1)*w0 + w1;
        ax += (cx - cj[0])*c;
        ay += (cy - cj[1])*c;
        az += (cz - cj[2])*c;
    }
    #pragma unroll
    for (int off = 16; off; off >>= 1) {
        ax += __shfl_xor_sync(0xffffffff, ax, off);
        ay += __shfl_xor_sync(0xffffffff, ay, off);
        az += __shfl_xor_sync(0xffffffff, az, off);
    }
    if (lane == 0) {
        float invn = 1.0f / (256.0f + 1e-6f);
        float* op = out + (b*Nc + i)*3;
        op[0] = cx + ax*invn;
        op[1] = cy + ay*invn;
        op[2] = cz + az*invn;
    }
}

// ---------------- energy head ----------------
__global__ __launch_bounds__(128) void energy_kernel(const float* __restrict__ h,
                                                     const float* __restrict__ enw,
                                                     const float* __restrict__ enb,
                                                     float* __restrict__ out) {
    int b = blockIdx.x;
    int tid = threadIdx.x;
    const float* row = h + (b*Nc)*Dc;
    float s = 0.f;
    #pragma unroll
    for (int j = 0; j < 4; j++) {
        int d = tid + 128*j;
        s += row[d]*enw[d];
    }
    #pragma unroll
    for (int off = 16; off; off >>= 1)
        s += __shfl_xor_sync(0xffffffff, s, off);
    __shared__ float rs[4];
    int wid = tid >> 5, lane = tid & 31;
    if (lane == 0) rs[wid] = s;
    __syncthreads();
    if (tid == 0)
        out[Bc*Nc*3 + b] = rs[0]+rs[1]+rs[2]+rs[3] + enb[0];
}

// ---------------- host ----------------
extern "C" void kernel_launch(void* const* d_in, const int* in_sizes, int n_in,
                              void* d_out, int out_size) {
    bool has_mask = (n_in >= 31);
    auto IN = [&](int i) -> const void* {
        int k = i;
        if (!has_mask && i > 3) k = i - 1;
        return d_in[k];
    };
    const int*   atom_types = (const int*)  IN(0);
    const float* coords     = (const float*)IN(1);
    const int*   pair_types = (const int*)  IN(2);
    const float* atom_emb   = (const float*)IN(4);
    const float* gmu        = (const float*)IN(5);
    const float* gsigma     = (const float*)IN(6);
    const float* pair_a     = (const float*)IN(7);
    const float* pair_b     = (const float*)IN(8);
    const float* pl_w       = (const float*)IN(9);
    const float* pl_b       = (const float*)IN(10);
    const float* ln1_g      = (const float*)IN(11);
    const float* ln1_b      = (const float*)IN(12);
    const float* qkv_w      = (const float*)IN(13);
    const float* qkv_b      = (const float*)IN(14);
    const float* pp_w       = (const float*)IN(15);
    const float* pp_b       = (const float*)IN(16);
    const float* out_w      = (const float*)IN(17);
    const float* out_b      = (const float*)IN(18);
    const float* ln2_g      = (const float*)IN(19);
    const float* ln2_b      = (const float*)IN(20);
    const float* ffn_w1     = (const float*)IN(21);
    const float* ffn_b1     = (const float*)IN(22);
    const float* ffn_w2     = (const float*)IN(23);
    const float* ffn_b2     = (const float*)IN(24);
    const float* se3_uw     = (const float*)IN(25);
    const float* se3_ub     = (const float*)IN(26);
    const float* se3_ww     = (const float*)IN(27);
    const float* se3_wb     = (const float*)IN(28);
    const float* en_w       = (const float*)IN(29);
    const float* en_b       = (const float*)IN(30);
    float* out = (float*)d_out;

    float *hb, *xb, *qkvb, *attnb, *ffnb, *pairb, *splitb;
    cudaGetSymbolAddress((void**)&hb,     g_h);
    cudaGetSymbolAddress((void**)&xb,     g_x);
    cudaGetSymbolAddress((void**)&qkvb,   g_qkv);
    cudaGetSymbolAddress((void**)&attnb,  g_attn);
    cudaGetSymbolAddress((void**)&ffnb,   g_ffn);
    cudaGetSymbolAddress((void**)&pairb,  g_pair);
    cudaGetSymbolAddress((void**)&splitb, g_split);

    cudaFuncSetAttribute(gemm_tf32_kernel,
                         cudaFuncAttributeMaxDynamicSharedMemorySize, SMEM_DYN);

    tab_kernel<<<(TABN + 256)/256, 256>>>(gmu, gsigma, pl_w, pl_b);
    emb_kernel<<<(Mc*Dc + 255)/256, 256>>>(atom_types, atom_emb, hb);
    pair_kernel<<<(Bc*Nc*Nc)/256, 256>>>(coords, pair_types, pair_a, pair_b, pairb);

    for (int l = 0; l < Lc; l++) {
        const float* l1g = ln1_g + l*Dc;
        const float* l1b = ln1_b + l*Dc;
        const float* qw  = qkv_w + (size_t)l*3*Dc*Dc;
        const float* qb  = qkv_b + l*3*Dc;
        const float* pwp = pp_w + l*Hc;
        const float* pbp = pp_b + l*Hc;
        const float* ow  = out_w + (size_t)l*Dc*Dc;
        const float* ob  = out_b + l*Dc;
        const float* l2g = ln2_g + l*Dc;
        const float* l2b = ln2_b + l*Dc;
        const float* w1  = ffn_w1 + (size_t)l*Fc*Dc;
        const float* b1  = ffn_b1 + l*Fc;
        const float* w2  = ffn_w2 + (size_t)l*Dc*Fc;
        const float* b2  = ffn_b2 + l*Dc;

        if (l == 0)
            ln_kernel<<<Mc, 128>>>(hb, l1g, l1b, xb);
        gemm_tf32_kernel<<<dim3((3*Dc)/BN, Mc/BM, 1), 256, SMEM_DYN>>>(
            xb, qw, nullptr, nullptr, qkvb, Mc, 3*Dc, Dc, 0);
        attn_kernel<<<dim3(Bc*Hc, 4), 256>>>(qkvb, qb, pairb, pwp, pbp, attnb);
        gemm_tf32_kernel<<<dim3(Dc/BN, Mc/BM, SPLITK), 256, SMEM_DYN>>>(
            attnb, ow, nullptr, nullptr, splitb, Mc, Dc, Dc, 0);
        reduce_ln_kernel<<<Mc, 128>>>(splitb, ob, hb, l2g, l2b, xb);
        gemm_tf32_kernel<<<dim3(Fc/BN, Mc/BM, 1), 256, SMEM_DYN>>>(
            xb, w1, b1, nullptr, ffnb, Mc, Fc, Dc, 1);
        gemm_tf32_kernel<<<dim3(Dc/BN, Mc/BM, SPLITK), 256, SMEM_DYN>>>(
            ffnb, w2, nullptr, nullptr, splitb, Mc, Dc, Fc, 0);
        if (l < Lc-1) {
            reduce_ln_kernel<<<Mc, 128>>>(splitb, b2, hb,
                                          ln1_g + (l+1)*Dc, ln1_b + (l+1)*Dc, xb);
        } else {
            reduce_splitk<<<(Mc*Dc/4 + 255)/256, 256>>>(splitb, b2, hb, Mc*Dc, Dc);
        }
    }

    coords_kernel<<<(Bc*Nc)/4, 128>>>(coords, pairb, se3_uw, se3_ub, se3_ww, se3_wb, out);
    energy_kernel<<<Bc, 128>>>(hb, en_w, en_b, out);
    (void)in_sizes; (void)out_size;
}

// round 13
// speedup vs baseline: 1.4278x; 1.4278x over previous
#include <cuda_runtime.h>
#include <cuda_fp16.h>
#include <mma.h>
#include <math.h>
#include <cstdint>
#include <stdint.h>

using namespace nvcuda;

// Problem constants
#define Lc 15
#define Dc 512
#define Hc 64
#define HDc 8
#define Fc 2048
#define Gc 128
#define Bc 4
#define Nc 256
#define Mc (Bc*Nc)   // 1024 rows
#define SPLITK 4
#define TABN 8192

// Weight split-region bases (elements) inside g_wh/g_wl
#define QKVB 0
#define OUTB 11796480
#define F1B  15728640
#define F2B  31457280
#define WTOT 47185920

// -------- scratch (device globals; no allocation allowed) --------
__device__ float g_h[Mc*Dc];
__device__ float g_qkv[Mc*3*Dc];
__device__ float g_pair[Bc*Nc*Nc];
__device__ float g_split[SPLITK*Mc*Dc];
__device__ float g_tab[TABN+1];
__device__ __half g_x16[Mc*Dc];     // LN outputs (fp16)
__device__ __half g_a16[Mc*Dc];     // attention outputs (fp16)
__device__ __half g_f16[Mc*Fc];     // FFN1/gelu outputs (fp16)
__device__ __half g_wh[WTOT], g_wl[WTOT];

// ---------------- gaussian table build ----------------
__global__ void tab_kernel(const float* __restrict__ mu,
                           const float* __restrict__ sigma,
                           const float* __restrict__ plw,
                           const float* __restrict__ plb) {
    int i = blockIdx.x*256 + threadIdx.x;
    if (i > TABN) return;
    float da = -8.0f + (float)i * (1.0f/512.0f);
    float s = 0.f;
    #pragma unroll 8
    for (int g = 0; g < Gc; g++) {
        float sg = sigma[g];
        float coef = plw[g] / (2.0f*sg*sg) / (sg * 2.5066282746310002f);
        float t = da - mu[g];
        s += __expf(-t*t) * coef;
    }
    g_tab[i] = s + plb[0];
}

// ---------------- pair representation via table lookup ----------------
__global__ void pair_kernel(const float* __restrict__ coords,
                            const int* __restrict__ ptypes,
                            const float* __restrict__ pa,
                            const float* __restrict__ pb,
                            float* __restrict__ pr) {
    int p = blockIdx.x * blockDim.x + threadIdx.x;
    int b = p >> 16;
    int rem = p & 65535;
    int i = rem >> 8, j = rem & 255;
    const float* ci = coords + (b*Nc + i)*3;
    const float* cj = coords + (b*Nc + j)*3;
    float dx = ci[0]-cj[0], dy = ci[1]-cj[1], dz = ci[2]-cj[2];
    float d2 = dx*dx + dy*dy + dz*dz;
    float dist = sqrtf(fmaxf(d2, 1e-12f));
    int pt = ptypes[p];
    float da = pa[pt]*dist + pb[pt];
    float t = (da + 8.0f) * 512.0f;
    t = fminf(fmaxf(t, 0.0f), (float)(TABN - 1));
    int idx = (int)t;
    float fr = t - (float)idx;
    float f0 = g_tab[idx], f1 = g_tab[idx+1];
    pr[p] = f0 + fr*(f1 - f0);
}

// ---------------- weight split: fp32 -> fp16 hi + exact-residue lo ----------------
__global__ void wsplit_kernel(const float* __restrict__ src,
                              __half* __restrict__ dh,
                              __half* __restrict__ dl, int n4) {
    int i = blockIdx.x*256 + threadIdx.x;
    if (i >= n4) return;
    float4 v = ((const float4*)src)[i];
    __half h0 = __float2half_rn(v.x), h1 = __float2half_rn(v.y);
    __half h2 = __float2half_rn(v.z), h3 = __float2half_rn(v.w);
    __half l0 = __float2half_rn(v.x - __half2float(h0));
    __half l1 = __float2half_rn(v.y - __half2float(h1));
    __half l2 = __float2half_rn(v.z - __half2float(h2));
    __half l3 = __float2half_rn(v.w - __half2float(h3));
    ((__half2*)dh)[i*2]   = __halves2half2(h0, h1);
    ((__half2*)dh)[i*2+1] = __halves2half2(h2, h3);
    ((__half2*)dl)[i*2]   = __halves2half2(l0, l1);
    ((__half2*)dl)[i*2+1] = __halves2half2(l2, l3);
}

// ---------------- embedding ----------------
__global__ void emb_kernel(const int* __restrict__ atom_types,
                           const float* __restrict__ atom_emb,
                           float* __restrict__ h) {
    int idx = blockIdx.x * blockDim.x + threadIdx.x;
    if (idx >= Mc*Dc) return;
    int row = idx >> 9;
    int d   = idx & 511;
    h[idx] = atom_emb[atom_types[row]*Dc + d];
}

// ---------------- layernorm (emits fp16) ----------------
__global__ __launch_bounds__(128) void ln_kernel(const float* __restrict__ in,
                                                 const float* __restrict__ g,
                                                 const float* __restrict__ bb,
                                                 __half* __restrict__ out) {
    int row = blockIdx.x;
    int tid = threadIdx.x;
    const float* x = in + row*Dc;
    float v[4], s = 0.f, s2 = 0.f;
    #pragma unroll
    for (int j = 0; j < 4; j++) {
        v[j] = x[tid + 128*j];
        s += v[j]; s2 += v[j]*v[j];
    }
    #pragma unroll
    for (int off = 16; off; off >>= 1) {
        s  += __shfl_xor_sync(0xffffffff, s,  off);
        s2 += __shfl_xor_sync(0xffffffff, s2, off);
    }
    __shared__ float rs[4], rs2[4];
    int wid = tid >> 5, lane = tid & 31;
    if (lane == 0) { rs[wid] = s; rs2[wid] = s2; }
    __syncthreads();
    s  = rs[0]+rs[1]+rs[2]+rs[3];
    s2 = rs2[0]+rs2[1]+rs2[2]+rs2[3];
    float mean = s * (1.0f/Dc);
    float var  = s2 * (1.0f/Dc) - mean*mean;
    float rstd = rsqrtf(var + 1e-5f);
    #pragma unroll
    for (int j = 0; j < 4; j++) {
        int d = tid + 128*j;
        out[row*Dc + d] = __float2half_rn((v[j]-mean)*rstd*g[d] + bb[d]);
    }
}

// ---------------- fused split-K reduce + layernorm (emits fp16) ----------------
__global__ __launch_bounds__(128) void reduce_ln_kernel(
    const float* __restrict__ P, const float* __restrict__ bias,
    float* __restrict__ h, const float* __restrict__ g,
    const float* __restrict__ bb, __half* __restrict__ xout) {
    int row = blockIdx.x;
    int tid = threadIdx.x;
    const int MN = Mc*Dc;
    float v[4], s = 0.f, s2 = 0.f;
    #pragma unroll
    for (int j = 0; j < 4; j++) {
        int d = tid + 128*j;
        int idx = row*Dc + d;
        float val = h[idx] + bias[d]
                  + P[idx] + P[idx + MN] + P[idx + 2*MN] + P[idx + 3*MN];
        h[idx] = val;
        v[j] = val; s += val; s2 += val*val;
    }
    #pragma unroll
    for (int off = 16; off; off >>= 1) {
        s  += __shfl_xor_sync(0xffffffff, s,  off);
        s2 += __shfl_xor_sync(0xffffffff, s2, off);
    }
    __shared__ float rs[4], rs2[4];
    int wid = tid >> 5, lane = tid & 31;
    if (lane == 0) { rs[wid] = s; rs2[wid] = s2; }
    __syncthreads();
    s  = rs[0]+rs[1]+rs[2]+rs[3];
    s2 = rs2[0]+rs2[1]+rs2[2]+rs2[3];
    float mean = s * (1.0f/Dc);
    float var  = s2 * (1.0f/Dc) - mean*mean;
    float rstd = rsqrtf(var + 1e-5f);
    #pragma unroll
    for (int j = 0; j < 4; j++) {
        int d = tid + 128*j;
        xout[row*Dc + d] = __float2half_rn((v[j]-mean)*rstd*g[d] + bb[d]);
    }
}

// ---------------- plain split-K reduce (final layer) ----------------
__global__ __launch_bounds__(256) void reduce_splitk(const float* __restrict__ P,
                                                     const float* __restrict__ bias,
                                                     float* __restrict__ h,
                                                     int MN, int N) {
    int i4 = blockIdx.x*256 + threadIdx.x;
    if (i4 >= MN/4) return;
    int n = (i4*4) & (N-1);
    const float4* P4 = (const float4*)P;
    int stride4 = MN/4;
    float4 s0 = P4[i4];
    float4 s1 = P4[i4 + stride4];
    float4 s2 = P4[i4 + 2*stride4];
    float4 s3 = P4[i4 + 3*stride4];
    float4 b  = *(const float4*)(bias + n);
    float4 hv = ((float4*)h)[i4];
    hv.x += s0.x + s1.x + s2.x + s3.x + b.x;
    hv.y += s0.y + s1.y + s2.y + s3.y + b.y;
    hv.z += s0.z + s1.z + s2.z + s3.z + b.z;
    hv.w += s0.w + s1.w + s2.w + s3.w + b.w;
    ((float4*)h)[i4] = hv;
}

// ---------------- fp16x2-weight GEMM: D = A*(Wh + Wl), fp32 acc ----------------
// A: fp16 (producer-rounded). Wh/Wl: pre-split fp16 (Wl = exact residue, subnormal ok).
// direct (bias==null && oh==null): raw fp32 frag stores (+z*M*N if split-K)
// staged: +bias [,gelu]; oh -> fp16 out; else fp32 C
#define BM 128
#define BN 64
#define BKT 32
#define LDA 40
#define LDC 68
#define SBUF 20480          // A 128*40*2 + Wh 64*40*2 + Wl 64*40*2
#define SMEM_DYN (2*SBUF)   // 40960
__global__ __launch_bounds__(256, 2) void gemm_fp16_kernel(
    const __half* __restrict__ A,
    const __half* __restrict__ Whg, const __half* __restrict__ Wlg,
    const float* __restrict__ bias,
    float* __restrict__ C, __half* __restrict__ oh,
    int M, int N, int K, int act)
{
    extern __shared__ __align__(16) char smem[];
    int tid = threadIdx.x;
    int m0 = blockIdx.y*BM, n0 = blockIdx.x*BN;
    int S = gridDim.z;
    int Ks = K / S;
    int kbeg = blockIdx.z * Ks;

    int wid = tid >> 5;
    int wm = (wid >> 1) * 32;
    int wn = (wid & 1) * 32;

    // staging map: A: idx = tid + i*256 (i=0,1), row = idx>>2, c = (idx&3)*8
    //              W: row = tid>>2, c = (tid&3)*8
    int ar = tid >> 2, ac = (tid & 3) * 8;
    const __half* pA0 = A   + (size_t)(m0+ar)*K + kbeg + ac;
    const __half* pA1 = pA0 + (size_t)64*K;
    const __half* pWh = Whg + (size_t)(n0+ar)*K + kbeg + ac;
    const __half* pWl = Wlg + (size_t)(n0+ar)*K + kbeg + ac;
    unsigned offA = (unsigned)(ar*LDA + ac);

    wmma::fragment<wmma::accumulator, 16, 16, 16, float> acc[2][2];
    #pragma unroll
    for (int i = 0; i < 2; i++)
        #pragma unroll
        for (int j = 0; j < 2; j++)
            wmma::fill_fragment(acc[i][j], 0.0f);

    // prefetch tile 0
    uint4 ra0 = *(const uint4*)pA0;
    uint4 ra1 = *(const uint4*)pA1;
    uint4 rh  = *(const uint4*)pWh;
    uint4 rl  = *(const uint4*)pWl;

    int nt = Ks / BKT;
    for (int t = 0; t < nt; t++) {
        char* buf = smem + (t & 1)*SBUF;
        __half* As = (__half*)buf;
        __half* Wh = As + BM*LDA;
        __half* Wl = Wh + BN*LDA;

        *(uint4*)&As[offA]          = ra0;
        *(uint4*)&As[offA + 64*LDA] = ra1;
        *(uint4*)&Wh[offA]          = rh;
        *(uint4*)&Wl[offA]          = rl;

        if (t + 1 < nt) {
            int k0 = (t+1)*BKT;
            ra0 = *(const uint4*)(pA0 + k0);
            ra1 = *(const uint4*)(pA1 + k0);
            rh  = *(const uint4*)(pWh + k0);
            rl  = *(const uint4*)(pWl + k0);
        }

        __syncthreads();   // the ONLY barrier per tile

        #pragma unroll
        for (int ks = 0; ks < BKT; ks += 16) {
            wmma::fragment<wmma::matrix_a, 16, 16, 16, __half, wmma::row_major> af[2];
            wmma::fragment<wmma::matrix_b, 16, 16, 16, __half, wmma::col_major> bh[2], bl[2];
            #pragma unroll
            for (int i = 0; i < 2; i++)
                wmma::load_matrix_sync(af[i], As + (wm + i*16)*LDA + ks, LDA);
            #pragma unroll
            for (int j = 0; j < 2; j++) {
                wmma::load_matrix_sync(bh[j], Wh + (wn + j*16)*LDA + ks, LDA);
                wmma::load_matrix_sync(bl[j], Wl + (wn + j*16)*LDA + ks, LDA);
            }
            // hi products first (different accs back-to-back), then lo products
            #pragma unroll
            for (int i = 0; i < 2; i++)
                #pragma unroll
                for (int j = 0; j < 2; j++)
                    wmma::mma_sync(acc[i][j], af[i], bh[j], acc[i][j]);
            #pragma unroll
            for (int i = 0; i < 2; i++)
                #pragma unroll
                for (int j = 0; j < 2; j++)
                    wmma::mma_sync(acc[i][j], af[i], bl[j], acc[i][j]);
        }
        // no trailing sync: next iter writes the other buffer
    }

    if (bias == nullptr && oh == nullptr) {
        float* Cp = C + (size_t)blockIdx.z*M*N;
        #pragma unroll
        for (int i = 0; i < 2; i++)
            #pragma unroll
            for (int j = 0; j < 2; j++)
                wmma::store_matrix_sync(Cp + (size_t)(m0+wm+i*16)*N + n0+wn+j*16,
                                        acc[i][j], N, wmma::mem_row_major);
        return;
    }

    __syncthreads();
    float* Ct = (float*)smem;   // 128*68*4 = 34816 <= 40960
    #pragma unroll
    for (int i = 0; i < 2; i++)
        #pragma unroll
        for (int j = 0; j < 2; j++)
            wmma::store_matrix_sync(Ct + (wm+i*16)*LDC + wn+j*16,
                                    acc[i][j], LDC, wmma::mem_row_major);
    __syncthreads();

    int col = (tid & 15) * 4;
    int r0  = tid >> 4;
    float4 bv = *(const float4*)(bias + n0 + col);
    #pragma unroll
    for (int rr = 0; rr < 8; rr++) {
        int row = rr*16 + r0;
        float vr[4];
        *(float4*)vr = *(const float4*)&Ct[row*LDC + col];
        vr[0] += bv.x; vr[1] += bv.y; vr[2] += bv.z; vr[3] += bv.w;
        if (act == 1) {
            #pragma unroll
            for (int j = 0; j < 4; j++)
                vr[j] = 0.5f * vr[j] * (1.0f + erff(vr[j] * 0.7071067811865475f));
        }
        size_t base = (size_t)(m0+row)*N + n0 + col;
        if (oh) {
            __half2 p0 = __halves2half2(__float2half_rn(vr[0]), __float2half_rn(vr[1]));
            __half2 p1 = __halves2half2(__float2half_rn(vr[2]), __float2half_rn(vr[3]));
            *(__half2*)&oh[base]   = p0;
            *(__half2*)&oh[base+2] = p1;
        } else {
            *(float4*)(C + base) = *(float4*)vr;
        }
    }
}

// ---------------- fused attention (QKV bias + scores + softmax + PV) ----------------
// output fp16 for the out-proj GEMM
__global__ __launch_bounds__(256) void attn_kernel(const float* __restrict__ qkv,
                                                   const float* __restrict__ qb,
                                                   const float* __restrict__ pr,
                                                   const float* __restrict__ ppw,
                                                   const float* __restrict__ ppb,
                                                   __half* __restrict__ out) {
    int b = blockIdx.x >> 6;
    int h = blockIdx.x & 63;
    __shared__ float Ks[Nc*9];
    __shared__ float Vs[Nc*9];
    int tid = threadIdx.x;
    float4 bq0 = *(const float4*)(qb + h*HDc);
    float4 bq1 = *(const float4*)(qb + h*HDc + 4);
    float4 bk0 = *(const float4*)(qb + Dc + h*HDc);
    float4 bk1 = *(const float4*)(qb + Dc + h*HDc + 4);
    float4 bv0 = *(const float4*)(qb + 2*Dc + h*HDc);
    float4 bv1 = *(const float4*)(qb + 2*Dc + h*HDc + 4);
    {
        int n = tid;
        const float* kp = qkv + (((b*Nc + n)*3 + 1))*Dc + h*HDc;
        const float* vp = kp + Dc;
        float4 k0 = *(const float4*)kp,     k1 = *(const float4*)(kp+4);
        float4 v0 = *(const float4*)vp,     v1 = *(const float4*)(vp+4);
        float* kd = &Ks[n*9];
        kd[0]=k0.x+bk0.x; kd[1]=k0.y+bk0.y; kd[2]=k0.z+bk0.z; kd[3]=k0.w+bk0.w;
        kd[4]=k1.x+bk1.x; kd[5]=k1.y+bk1.y; kd[6]=k1.z+bk1.z; kd[7]=k1.w+bk1.w;
        float* vd = &Vs[n*9];
        vd[0]=v0.x+bv0.x; vd[1]=v0.y+bv0.y; vd[2]=v0.z+bv0.z; vd[3]=v0.w+bv0.w;
        vd[4]=v1.x+bv1.x; vd[5]=v1.y+bv1.y; vd[6]=v1.z+bv1.z; vd[7]=v1.w+bv1.w;
    }
    __syncthreads();
    const float scale = 0.3535533905932738f;
    float pw = ppw[h], pb = ppb[h];
    int warp = tid >> 5, lane = tid & 31;
    #pragma unroll
    for (int r = 0; r < 8; r++) {
        int i = blockIdx.y*64 + warp*8 + r;
        const float* qp = qkv + ((b*Nc + i)*3)*Dc + h*HDc;
        float4 q0 = *(const float4*)qp, q1 = *(const float4*)(qp+4);
        float qr[8];
        qr[0]=q0.x+bq0.x; qr[1]=q0.y+bq0.y; qr[2]=q0.z+bq0.z; qr[3]=q0.w+bq0.w;
        qr[4]=q1.x+bq1.x; qr[5]=q1.y+bq1.y; qr[6]=q1.z+bq1.z; qr[7]=q1.w+bq1.w;
        const float* prow = pr + (b*Nc + i)*Nc;
        float s[8];
        float mx = -1e30f;
        #pragma unroll
        for (int jj = 0; jj < 8; jj++) {
            int j = lane + 32*jj;
            const float* kk = &Ks[j*9];
            float d = qr[0]*kk[0] + qr[1]*kk[1] + qr[2]*kk[2] + qr[3]*kk[3]
                    + qr[4]*kk[4] + qr[5]*kk[5] + qr[6]*kk[6] + qr[7]*kk[7];
            s[jj] = d*scale + prow[j]*pw + pb;
            mx = fmaxf(mx, s[jj]);
        }
        #pragma unroll
        for (int off = 16; off; off >>= 1)
            mx = fmaxf(mx, __shfl_xor_sync(0xffffffff, mx, off));
        float sum = 0.f;
        #pragma unroll
        for (int jj = 0; jj < 8; jj++) { s[jj] = __expf(s[jj]-mx); sum += s[jj]; }
        #pragma unroll
        for (int off = 16; off; off >>= 1)
            sum += __shfl_xor_sync(0xffffffff, sum, off);
        float inv = 1.0f / sum;
        float acc[8] = {};
        #pragma unroll
        for (int jj = 0; jj < 8; jj++) {
            int j = lane + 32*jj;
            float p = s[jj]*inv;
            const float* vv = &Vs[j*9];
            #pragma unroll
            for (int d = 0; d < 8; d++) acc[d] += p*vv[d];
        }
        #pragma unroll
        for (int off = 16; off; off >>= 1) {
            #pragma unroll
            for (int d = 0; d < 8; d++)
                acc[d] += __shfl_xor_sync(0xffffffff, acc[d], off);
        }
        if (lane == 0) {
            __half* op = out + (size_t)(b*Nc + i)*Dc + h*HDc;
            #pragma unroll
            for (int d = 0; d < 8; d++) op[d] = __float2half_rn(acc[d]);
        }
    }
}

// ---------------- SE(3) coordinate update ----------------
__global__ __launch_bounds__(128) void coords_kernel(const float* __restrict__ coords,
                                                     const float* __restrict__ pr,
                                                     const float* __restrict__ uw,
                                                     const float* __restrict__ ub,
                                                     const float* __restrict__ ww,
                                                     const float* __restrict__ wb,
                                                     float* __restrict__ out) {
    int gw = blockIdx.x * 4 + (threadIdx.x >> 5);
    int lane = threadIdx.x & 31;
    int b = gw >> 8, i = gw & 255;
    float u0 = uw[0], u1 = ub[0], w0 = ww[0], w1 = wb[0];
    const float* ci = coords + (b*Nc + i)*3;
    float cx = ci[0], cy = ci[1], cz = ci[2];
    float ax = 0.f, ay = 0.f, az = 0.f;
    const float* prow = pr + (b*Nc + i)*Nc;
    #pragma unroll
    for (int jj = 0; jj < 8; jj++) {
        int j = lane + 32*jj;
        const float* cj = coords + (b*Nc + j)*3;
        float c = (fmaxf(prow[j], 0.f)*u0 + u1)*w0 + w1;
        ax += (cx - cj[0])*c;
        ay += (cy - cj[1])*c;
        az += (cz - cj[2])*c;
    }
    #pragma unroll
    for (int off = 16; off; off >>= 1) {
        ax += __shfl_xor_sync(0xffffffff, ax, off);
        ay += __shfl_xor_sync(0xffffffff, ay, off);
        az += __shfl_xor_sync(0xffffffff, az, off);
    }
    if (lane == 0) {
        float invn = 1.0f / (256.0f + 1e-6f);
        float* op = out + (b*Nc + i)*3;
        op[0] = cx + ax*invn;
        op[1] = cy + ay*invn;
        op[2] = cz + az*invn;
    }
}

// ---------------- energy head ----------------
__global__ __launch_bounds__(128) void energy_kernel(const float* __restrict__ h,
                                                     const float* __restrict__ enw,
                                                     const float* __restrict__ enb,
                                                     float* __restrict__ out) {
    int b = blockIdx.x;
    int tid = threadIdx.x;
    const float* row = h + (b*Nc)*Dc;
    float s = 0.f;
    #pragma unroll
    for (int j = 0; j < 4; j++) {
        int d = tid + 128*j;
        s += row[d]*enw[d];
    }
    #pragma unroll
    for (int off = 16; off; off >>= 1)
        s += __shfl_xor_sync(0xffffffff, s, off);
    __shared__ float rs[4];
    int wid = tid >> 5, lane = tid & 31;
    if (lane == 0) rs[wid] = s;
    __syncthreads();
    if (tid == 0)
        out[Bc*Nc*3 + b] = rs[0]+rs[1]+rs[2]+rs[3] + enb[0];
}

// ---------------- host ----------------
extern "C" void kernel_launch(void* const* d_in, const int* in_sizes, int n_in,
                              void* d_out, int out_size) {
    bool has_mask = (n_in >= 31);
    auto IN = [&](int i) -> const void* {
        int k = i;
        if (!has_mask && i > 3) k = i - 1;
        return d_in[k];
    };
    const int*   atom_types = (const int*)  IN(0);
    const float* coords     = (const float*)IN(1);
    const int*   pair_types = (const int*)  IN(2);
    const float* atom_emb   = (const float*)IN(4);
    const float* gmu        = (const float*)IN(5);
    const float* gsigma     = (const float*)IN(6);
    const float* pair_a     = (const float*)IN(7);
    const float* pair_b     = (const float*)IN(8);
    const float* pl_w       = (const float*)IN(9);
    const float* pl_b       = (const float*)IN(10);
    const float* ln1_g      = (const float*)IN(11);
    const float* ln1_b      = (const float*)IN(12);
    const float* qkv_w      = (const float*)IN(13);
    const float* qkv_b      = (const float*)IN(14);
    const float* pp_w       = (const float*)IN(15);
    const float* pp_b       = (const float*)IN(16);
    const float* out_w      = (const float*)IN(17);
    const float* out_b      = (const float*)IN(18);
    const float* ln2_g      = (const float*)IN(19);
    const float* ln2_b      = (const float*)IN(20);
    const float* ffn_w1     = (const float*)IN(21);
    const float* ffn_b1     = (const float*)IN(22);
    const float* ffn_w2     = (const float*)IN(23);
    const float* ffn_b2     = (const float*)IN(24);
    const float* se3_uw     = (const float*)IN(25);
    const float* se3_ub     = (const float*)IN(26);
    const float* se3_ww     = (const float*)IN(27);
    const float* se3_wb     = (const float*)IN(28);
    const float* en_w       = (const float*)IN(29);
    const float* en_b       = (const float*)IN(30);
    float* out = (float*)d_out;

    float *hb, *qkvb, *pairb, *splitb;
    __half *x16, *a16, *f16, *wh, *wl;
    cudaGetSymbolAddress((void**)&hb,     g_h);
    cudaGetSymbolAddress((void**)&qkvb,   g_qkv);
    cudaGetSymbolAddress((void**)&pairb,  g_pair);
    cudaGetSymbolAddress((void**)&splitb, g_split);
    cudaGetSymbolAddress((void**)&x16, g_x16);
    cudaGetSymbolAddress((void**)&a16, g_a16);
    cudaGetSymbolAddress((void**)&f16, g_f16);
    cudaGetSymbolAddress((void**)&wh,  g_wh);
    cudaGetSymbolAddress((void**)&wl,  g_wl);

    cudaFuncSetAttribute(gemm_fp16_kernel,
                         cudaFuncAttributeMaxDynamicSharedMemorySize, SMEM_DYN);

    // pre-split all weights into fp16 hi + residue lo (once per call)
    wsplit_kernel<<<(11796480/4 + 255)/256, 256>>>(qkv_w,  wh + QKVB, wl + QKVB, 11796480/4);
    wsplit_kernel<<<( 3932160/4 + 255)/256, 256>>>(out_w,  wh + OUTB, wl + OUTB,  3932160/4);
    wsplit_kernel<<<(15728640/4 + 255)/256, 256>>>(ffn_w1, wh + F1B,  wl + F1B,  15728640/4);
    wsplit_kernel<<<(15728640/4 + 255)/256, 256>>>(ffn_w2, wh + F2B,  wl + F2B,  15728640/4);

    tab_kernel<<<(TABN + 256)/256, 256>>>(gmu, gsigma, pl_w, pl_b);
    emb_kernel<<<(Mc*Dc + 255)/256, 256>>>(atom_types, atom_emb, hb);
    pair_kernel<<<(Bc*Nc*Nc)/256, 256>>>(coords, pair_types, pair_a, pair_b, pairb);

    for (int l = 0; l < Lc; l++) {
        const float* qb  = qkv_b + l*3*Dc;
        const float* pwp = pp_w + l*Hc;
        const float* pbp = pp_b + l*Hc;
        const float* ob  = out_b + l*Dc;
        const float* l2g = ln2_g + l*Dc;
        const float* l2b = ln2_b + l*Dc;
        const float* b1  = ffn_b1 + l*Fc;
        const float* b2  = ffn_b2 + l*Dc;
        const __half* qwh = wh + QKVB + (size_t)l*786432;
        const __half* qwl = wl + QKVB + (size_t)l*786432;
        const __half* owh = wh + OUTB + (size_t)l*262144;
        const __half* owl = wl + OUTB + (size_t)l*262144;
        const __half* w1h = wh + F1B  + (size_t)l*1048576;
        const __half* w1l = wl + F1B  + (size_t)l*1048576;
        const __half* w2h = wh + F2B  + (size_t)l*1048576;
        const __half* w2l = wl + F2B  + (size_t)l*1048576;

        if (l == 0)
            ln_kernel<<<Mc, 128>>>(hb, ln1_g, ln1_b, x16);
        gemm_fp16_kernel<<<dim3((3*Dc)/BN, Mc/BM, 1), 256, SMEM_DYN>>>(
            x16, qwh, qwl, nullptr, qkvb, nullptr, Mc, 3*Dc, Dc, 0);
        attn_kernel<<<dim3(Bc*Hc, 4), 256>>>(qkvb, qb, pairb, pwp, pbp, a16);
        gemm_fp16_kernel<<<dim3(Dc/BN, Mc/BM, SPLITK), 256, SMEM_DYN>>>(
            a16, owh, owl, nullptr, splitb, nullptr, Mc, Dc, Dc, 0);
        reduce_ln_kernel<<<Mc, 128>>>(splitb, ob, hb, l2g, l2b, x16);
        gemm_fp16_kernel<<<dim3(Fc/BN, Mc/BM, 1), 256, SMEM_DYN>>>(
            x16, w1h, w1l, b1, nullptr, f16, Mc, Fc, Dc, 1);
        gemm_fp16_kernel<<<dim3(Dc/BN, Mc/BM, SPLITK), 256, SMEM_DYN>>>(
            f16, w2h, w2l, nullptr, splitb, nullptr, Mc, Dc, Fc, 0);
        if (l < Lc-1) {
            reduce_ln_kernel<<<Mc, 128>>>(splitb, b2, hb,
                                          ln1_g + (l+1)*Dc, ln1_b + (l+1)*Dc, x16);
        } else {
            reduce_splitk<<<(Mc*Dc/4 + 255)/256, 256>>>(splitb, b2, hb, Mc*Dc, Dc);
        }
    }

    coords_kernel<<<(Bc*Nc)/4, 128>>>(coords, pairb, se3_uw, se3_ub, se3_ww, se3_wb, out);
    energy_kernel<<<Bc, 128>>>(hb, en_w, en_b, out);
    (void)in_sizes; (void)out_size;
}

// round 15
// speedup vs baseline: 1.5740x; 1.1024x over previous
#include <cuda_runtime.h>
#include <cuda_fp16.h>
#include <mma.h>
#include <math.h>
#include <cstdint>
#include <stdint.h>

using namespace nvcuda;

// Problem constants
#define Lc 15
#define Dc 512
#define Hc 64
#define HDc 8
#define Fc 2048
#define Gc 128
#define Bc 4
#define Nc 256
#define Mc (Bc*Nc)   // 1024 rows
#define SPLITK 4
#define TABN 8192

// Weight region bases (elements) inside g_wh
#define QKVB 0
#define OUTB 11796480
#define F1B  15728640
#define F2B  31457280
#define WTOT 47185920

// -------- scratch (device globals; no allocation allowed) --------
__device__ float g_h[Mc*Dc];
__device__ float g_qkv[Mc*3*Dc];
__device__ float g_pair[Bc*Nc*Nc];
__device__ float g_split[SPLITK*Mc*Dc];
__device__ float g_tab[TABN+1];
__device__ __half g_x16[Mc*Dc];     // LN outputs (fp16)
__device__ __half g_a16[Mc*Dc];     // attention outputs (fp16)
__device__ __half g_f16[Mc*Fc];     // FFN1/gelu outputs (fp16)
__device__ __half g_wh[WTOT];

// ---------------- gaussian table build ----------------
__global__ void tab_kernel(const float* __restrict__ mu,
                           const float* __restrict__ sigma,
                           const float* __restrict__ plw,
                           const float* __restrict__ plb) {
    int i = blockIdx.x*256 + threadIdx.x;
    if (i > TABN) return;
    float da = -8.0f + (float)i * (1.0f/512.0f);
    float s = 0.f;
    #pragma unroll 8
    for (int g = 0; g < Gc; g++) {
        float sg = sigma[g];
        float coef = plw[g] / (2.0f*sg*sg) / (sg * 2.5066282746310002f);
        float t = da - mu[g];
        s += __expf(-t*t) * coef;
    }
    g_tab[i] = s + plb[0];
}

// ---------------- pair representation via table lookup ----------------
__global__ void pair_kernel(const float* __restrict__ coords,
                            const int* __restrict__ ptypes,
                            const float* __restrict__ pa,
                            const float* __restrict__ pb,
                            float* __restrict__ pr) {
    int p = blockIdx.x * blockDim.x + threadIdx.x;
    int b = p >> 16;
    int rem = p & 65535;
    int i = rem >> 8, j = rem & 255;
    const float* ci = coords + (b*Nc + i)*3;
    const float* cj = coords + (b*Nc + j)*3;
    float dx = ci[0]-cj[0], dy = ci[1]-cj[1], dz = ci[2]-cj[2];
    float d2 = dx*dx + dy*dy + dz*dz;
    float dist = sqrtf(fmaxf(d2, 1e-12f));
    int pt = ptypes[p];
    float da = pa[pt]*dist + pb[pt];
    float t = (da + 8.0f) * 512.0f;
    t = fminf(fmaxf(t, 0.0f), (float)(TABN - 1));
    int idx = (int)t;
    float fr = t - (float)idx;
    float f0 = g_tab[idx], f1 = g_tab[idx+1];
    pr[p] = f0 + fr*(f1 - f0);
}

// ---------------- weight convert: fp32 -> fp16 (RNE) ----------------
__global__ void wconv_kernel(const float* __restrict__ src,
                             __half* __restrict__ dh, int n4) {
    int i = blockIdx.x*256 + threadIdx.x;
    if (i >= n4) return;
    float4 v = ((const float4*)src)[i];
    ((__half2*)dh)[i*2]   = __halves2half2(__float2half_rn(v.x), __float2half_rn(v.y));
    ((__half2*)dh)[i*2+1] = __halves2half2(__float2half_rn(v.z), __float2half_rn(v.w));
}

// ---------------- embedding ----------------
__global__ void emb_kernel(const int* __restrict__ atom_types,
                           const float* __restrict__ atom_emb,
                           float* __restrict__ h) {
    int idx = blockIdx.x * blockDim.x + threadIdx.x;
    if (idx >= Mc*Dc) return;
    int row = idx >> 9;
    int d   = idx & 511;
    h[idx] = atom_emb[atom_types[row]*Dc + d];
}

// ---------------- layernorm (emits fp16) ----------------
__global__ __launch_bounds__(128) void ln_kernel(const float* __restrict__ in,
                                                 const float* __restrict__ g,
                                                 const float* __restrict__ bb,
                                                 __half* __restrict__ out) {
    int row = blockIdx.x;
    int tid = threadIdx.x;
    const float* x = in + row*Dc;
    float v[4], s = 0.f, s2 = 0.f;
    #pragma unroll
    for (int j = 0; j < 4; j++) {
        v[j] = x[tid + 128*j];
        s += v[j]; s2 += v[j]*v[j];
    }
    #pragma unroll
    for (int off = 16; off; off >>= 1) {
        s  += __shfl_xor_sync(0xffffffff, s,  off);
        s2 += __shfl_xor_sync(0xffffffff, s2, off);
    }
    __shared__ float rs[4], rs2[4];
    int wid = tid >> 5, lane = tid & 31;
    if (lane == 0) { rs[wid] = s; rs2[wid] = s2; }
    __syncthreads();
    s  = rs[0]+rs[1]+rs[2]+rs[3];
    s2 = rs2[0]+rs2[1]+rs2[2]+rs2[3];
    float mean = s * (1.0f/Dc);
    float var  = s2 * (1.0f/Dc) - mean*mean;
    float rstd = rsqrtf(var + 1e-5f);
    #pragma unroll
    for (int j = 0; j < 4; j++) {
        int d = tid + 128*j;
        out[row*Dc + d] = __float2half_rn((v[j]-mean)*rstd*g[d] + bb[d]);
    }
}

// ---------------- fused split-K reduce + layernorm (emits fp16) ----------------
__global__ __launch_bounds__(128) void reduce_ln_kernel(
    const float* __restrict__ P, const float* __restrict__ bias,
    float* __restrict__ h, const float* __restrict__ g,
    const float* __restrict__ bb, __half* __restrict__ xout) {
    int row = blockIdx.x;
    int tid = threadIdx.x;
    const int MN = Mc*Dc;
    float v[4], s = 0.f, s2 = 0.f;
    #pragma unroll
    for (int j = 0; j < 4; j++) {
        int d = tid + 128*j;
        int idx = row*Dc + d;
        float val = h[idx] + bias[d]
                  + P[idx] + P[idx + MN] + P[idx + 2*MN] + P[idx + 3*MN];
        h[idx] = val;
        v[j] = val; s += val; s2 += val*val;
    }
    #pragma unroll
    for (int off = 16; off; off >>= 1) {
        s  += __shfl_xor_sync(0xffffffff, s,  off);
        s2 += __shfl_xor_sync(0xffffffff, s2, off);
    }
    __shared__ float rs[4], rs2[4];
    int wid = tid >> 5, lane = tid & 31;
    if (lane == 0) { rs[wid] = s; rs2[wid] = s2; }
    __syncthreads();
    s  = rs[0]+rs[1]+rs[2]+rs[3];
    s2 = rs2[0]+rs2[1]+rs2[2]+rs2[3];
    float mean = s * (1.0f/Dc);
    float var  = s2 * (1.0f/Dc) - mean*mean;
    float rstd = rsqrtf(var + 1e-5f);
    #pragma unroll
    for (int j = 0; j < 4; j++) {
        int d = tid + 128*j;
        xout[row*Dc + d] = __float2half_rn((v[j]-mean)*rstd*g[d] + bb[d]);
    }
}

// ---------------- plain split-K reduce (final layer) ----------------
__global__ __launch_bounds__(256) void reduce_splitk(const float* __restrict__ P,
                                                     const float* __restrict__ bias,
                                                     float* __restrict__ h,
                                                     int MN, int N) {
    int i4 = blockIdx.x*256 + threadIdx.x;
    if (i4 >= MN/4) return;
    int n = (i4*4) & (N-1);
    const float4* P4 = (const float4*)P;
    int stride4 = MN/4;
    float4 s0 = P4[i4];
    float4 s1 = P4[i4 + stride4];
    float4 s2 = P4[i4 + 2*stride4];
    float4 s3 = P4[i4 + 3*stride4];
    float4 b  = *(const float4*)(bias + n);
    float4 hv = ((float4*)h)[i4];
    hv.x += s0.x + s1.x + s2.x + s3.x + b.x;
    hv.y += s0.y + s1.y + s2.y + s3.y + b.y;
    hv.z += s0.z + s1.z + s2.z + s3.z + b.z;
    hv.w += s0.w + s1.w + s2.w + s3.w + b.w;
    ((float4*)h)[i4] = hv;
}

// ---------------- pure fp16 GEMM: D = A*W^T, fp32 acc ----------------
// A, W: fp16 (RNE-rounded). direct (bias==null && oh==null): raw fp32 frag
// stores (+z*M*N if split-K). staged: +bias [,gelu]; oh -> fp16 out; else fp32 C.
#define BM 128
#define BN 64
#define BKT 32
#define LDA 40
#define LDC 68
#define SBUF 15360           // A 128*40*2 + W 64*40*2
#define SMEM_DYN 34816       // max(2*SBUF = 30720, epilogue 128*LDC*4 = 34816)
__global__ __launch_bounds__(256, 2) void gemm_fp16_kernel(
    const __half* __restrict__ A, const __half* __restrict__ Wg,
    const float* __restrict__ bias,
    float* __restrict__ C, __half* __restrict__ oh,
    int M, int N, int K, int act)
{
    extern __shared__ __align__(16) char smem[];
    int tid = threadIdx.x;
    int m0 = blockIdx.y*BM, n0 = blockIdx.x*BN;
    int S = gridDim.z;
    int Ks = K / S;
    int kbeg = blockIdx.z * Ks;

    int wid = tid >> 5;
    int wm = (wid >> 1) * 32;
    int wn = (wid & 1) * 32;

    int ar = tid >> 2, ac = (tid & 3) * 8;
    const __half* pA0 = A  + (size_t)(m0+ar)*K + kbeg + ac;
    const __half* pA1 = pA0 + (size_t)64*K;
    const __half* pW  = Wg + (size_t)(n0+ar)*K + kbeg + ac;
    unsigned offA = (unsigned)(ar*LDA + ac);

    wmma::fragment<wmma::accumulator, 16, 16, 16, float> acc[2][2];
    #pragma unroll
    for (int i = 0; i < 2; i++)
        #pragma unroll
        for (int j = 0; j < 2; j++)
            wmma::fill_fragment(acc[i][j], 0.0f);

    uint4 ra0 = *(const uint4*)pA0;
    uint4 ra1 = *(const uint4*)pA1;
    uint4 rw  = *(const uint4*)pW;

    int nt = Ks / BKT;
    for (int t = 0; t < nt; t++) {
        char* buf = smem + (t & 1)*SBUF;
        __half* As = (__half*)buf;
        __half* Ws = As + BM*LDA;

        *(uint4*)&As[offA]          = ra0;
        *(uint4*)&As[offA + 64*LDA] = ra1;
        *(uint4*)&Ws[offA]          = rw;

        if (t + 1 < nt) {
            int k0 = (t+1)*BKT;
            ra0 = *(const uint4*)(pA0 + k0);
            ra1 = *(const uint4*)(pA1 + k0);
            rw  = *(const uint4*)(pW + k0);
        }

        __syncthreads();   // the ONLY barrier per tile

        #pragma unroll
        for (int ks = 0; ks < BKT; ks += 16) {
            wmma::fragment<wmma::matrix_a, 16, 16, 16, __half, wmma::row_major> af[2];
            wmma::fragment<wmma::matrix_b, 16, 16, 16, __half, wmma::col_major> bf[2];
            #pragma unroll
            for (int i = 0; i < 2; i++)
                wmma::load_matrix_sync(af[i], As + (wm + i*16)*LDA + ks, LDA);
            #pragma unroll
            for (int j = 0; j < 2; j++)
                wmma::load_matrix_sync(bf[j], Ws + (wn + j*16)*LDA + ks, LDA);
            #pragma unroll
            for (int i = 0; i < 2; i++)
                #pragma unroll
                for (int j = 0; j < 2; j++)
                    wmma::mma_sync(acc[i][j], af[i], bf[j], acc[i][j]);
        }
        // no trailing sync: next iter writes the other buffer
    }

    if (bias == nullptr && oh == nullptr) {
        float* Cp = C + (size_t)blockIdx.z*M*N;
        #pragma unroll
        for (int i = 0; i < 2; i++)
            #pragma unroll
            for (int j = 0; j < 2; j++)
                wmma::store_matrix_sync(Cp + (size_t)(m0+wm+i*16)*N + n0+wn+j*16,
                                        acc[i][j], N, wmma::mem_row_major);
        return;
    }

    __syncthreads();
    float* Ct = (float*)smem;   // 128*68*4 = 34816 = SMEM_DYN
    #pragma unroll
    for (int i = 0; i < 2; i++)
        #pragma unroll
        for (int j = 0; j < 2; j++)
            wmma::store_matrix_sync(Ct + (wm+i*16)*LDC + wn+j*16,
                                    acc[i][j], LDC, wmma::mem_row_major);
    __syncthreads();

    int col = (tid & 15) * 4;
    int r0  = tid >> 4;
    float4 bv = *(const float4*)(bias + n0 + col);
    #pragma unroll
    for (int rr = 0; rr < 8; rr++) {
        int row = rr*16 + r0;
        float vr[4];
        *(float4*)vr = *(const float4*)&Ct[row*LDC + col];
        vr[0] += bv.x; vr[1] += bv.y; vr[2] += bv.z; vr[3] += bv.w;
        if (act == 1) {
            #pragma unroll
            for (int j = 0; j < 4; j++)
                vr[j] = 0.5f * vr[j] * (1.0f + erff(vr[j] * 0.7071067811865475f));
        }
        size_t base = (size_t)(m0+row)*N + n0 + col;
        if (oh) {
            __half2 p0 = __halves2half2(__float2half_rn(vr[0]), __float2half_rn(vr[1]));
            __half2 p1 = __halves2half2(__float2half_rn(vr[2]), __float2half_rn(vr[3]));
            *(__half2*)&oh[base]   = p0;
            *(__half2*)&oh[base+2] = p1;
        } else {
            *(float4*)(C + base) = *(float4*)vr;
        }
    }
}

// ---------------- fused attention (QKV bias + scores + softmax + PV) ----------------
__global__ __launch_bounds__(256) void attn_kernel(const float* __restrict__ qkv,
                                                   const float* __restrict__ qb,
                                                   const float* __restrict__ pr,
                                                   const float* __restrict__ ppw,
                                                   const float* __restrict__ ppb,
                                                   __half* __restrict__ out) {
    int b = blockIdx.x >> 6;
    int h = blockIdx.x & 63;
    __shared__ float Ks[Nc*9];
    __shared__ float Vs[Nc*9];
    int tid = threadIdx.x;
    float4 bq0 = *(const float4*)(qb + h*HDc);
    float4 bq1 = *(const float4*)(qb + h*HDc + 4);
    float4 bk0 = *(const float4*)(qb + Dc + h*HDc);
    float4 bk1 = *(const float4*)(qb + Dc + h*HDc + 4);
    float4 bv0 = *(const float4*)(qb + 2*Dc + h*HDc);
    float4 bv1 = *(const float4*)(qb + 2*Dc + h*HDc + 4);
    {
        int n = tid;
        const float* kp = qkv + (((b*Nc + n)*3 + 1))*Dc + h*HDc;
        const float* vp = kp + Dc;
        float4 k0 = *(const float4*)kp,     k1 = *(const float4*)(kp+4);
        float4 v0 = *(const float4*)vp,     v1 = *(const float4*)(vp+4);
        float* kd = &Ks[n*9];
        kd[0]=k0.x+bk0.x; kd[1]=k0.y+bk0.y; kd[2]=k0.z+bk0.z; kd[3]=k0.w+bk0.w;
        kd[4]=k1.x+bk1.x; kd[5]=k1.y+bk1.y; kd[6]=k1.z+bk1.z; kd[7]=k1.w+bk1.w;
        float* vd = &Vs[n*9];
        vd[0]=v0.x+bv0.x; vd[1]=v0.y+bv0.y; vd[2]=v0.z+bv0.z; vd[3]=v0.w+bv0.w;
        vd[4]=v1.x+bv1.x; vd[5]=v1.y+bv1.y; vd[6]=v1.z+bv1.z; vd[7]=v1.w+bv1.w;
    }
    __syncthreads();
    const float scale = 0.3535533905932738f;
    float pw = ppw[h], pb = ppb[h];
    int warp = tid >> 5, lane = tid & 31;
    #pragma unroll
    for (int r = 0; r < 8; r++) {
        int i = blockIdx.y*64 + warp*8 + r;
        const float* qp = qkv + ((b*Nc + i)*3)*Dc + h*HDc;
        float4 q0 = *(const float4*)qp, q1 = *(const float4*)(qp+4);
        float qr[8];
        qr[0]=q0.x+bq0.x; qr[1]=q0.y+bq0.y; qr[2]=q0.z+bq0.z; qr[3]=q0.w+bq0.w;
        qr[4]=q1.x+bq1.x; qr[5]=q1.y+bq1.y; qr[6]=q1.z+bq1.z; qr[7]=q1.w+bq1.w;
        const float* prow = pr + (b*Nc + i)*Nc;
        float s[8];
        float mx = -1e30f;
        #pragma unroll
        for (int jj = 0; jj < 8; jj++) {
            int j = lane + 32*jj;
            const float* kk = &Ks[j*9];
            float d = qr[0]*kk[0] + qr[1]*kk[1] + qr[2]*kk[2] + qr[3]*kk[3]
                    + qr[4]*kk[4] + qr[5]*kk[5] + qr[6]*kk[6] + qr[7]*kk[7];
            s[jj] = d*scale + prow[j]*pw + pb;
            mx = fmaxf(mx, s[jj]);
        }
        #pragma unroll
        for (int off = 16; off; off >>= 1)
            mx = fmaxf(mx, __shfl_xor_sync(0xffffffff, mx, off));
        float sum = 0.f;
        #pragma unroll
        for (int jj = 0; jj < 8; jj++) { s[jj] = __expf(s[jj]-mx); sum += s[jj]; }
        #pragma unroll
        for (int off = 16; off; off >>= 1)
            sum += __shfl_xor_sync(0xffffffff, sum, off);
        float inv = 1.0f / sum;
        float acc[8] = {};
        #pragma unroll
        for (int jj = 0; jj < 8; jj++) {
            int j = lane + 32*jj;
            float p = s[jj]*inv;
            const float* vv = &Vs[j*9];
            #pragma unroll
            for (int d = 0; d < 8; d++) acc[d] += p*vv[d];
        }
        #pragma unroll
        for (int off = 16; off; off >>= 1) {
            #pragma unroll
            for (int d = 0; d < 8; d++)
                acc[d] += __shfl_xor_sync(0xffffffff, acc[d], off);
        }
        if (lane == 0) {
            __half* op = out + (size_t)(b*Nc + i)*Dc + h*HDc;
            #pragma unroll
            for (int d = 0; d < 8; d++) op[d] = __float2half_rn(acc[d]);
        }
    }
}

// ---------------- SE(3) coordinate update ----------------
__global__ __launch_bounds__(128) void coords_kernel(const float* __restrict__ coords,
                                                     const float* __restrict__ pr,
                                                     const float* __restrict__ uw,
                                                     const float* __restrict__ ub,
                                                     const float* __restrict__ ww,
                                                     const float* __restrict__ wb,
                                                     float* __restrict__ out) {
    int gw = blockIdx.x * 4 + (threadIdx.x >> 5);
    int lane = threadIdx.x & 31;
    int b = gw >> 8, i = gw & 255;
    float u0 = uw[0], u1 = ub[0], w0 = ww[0], w1 = wb[0];
    const float* ci = coords + (b*Nc + i)*3;
    float cx = ci[0], cy = ci[1], cz = ci[2];
    float ax = 0.f, ay = 0.f, az = 0.f;
    const float* prow = pr + (b*Nc + i)*Nc;
    #pragma unroll
    for (int jj = 0; jj < 8; jj++) {
        int j = lane + 32*jj;
        const float* cj = coords + (b*Nc + j)*3;
        float c = (fmaxf(prow[j], 0.f)*u0 + u1)*w0 + w1;
        ax += (cx - cj[0])*c;
        ay += (cy - cj[1])*c;
        az += (cz - cj[2])*c;
    }
    #pragma unroll
    for (int off = 16; off; off >>= 1) {
        ax += __shfl_xor_sync(0xffffffff, ax, off);
        ay += __shfl_xor_sync(0xffffffff, ay, off);
        az += __shfl_xor_sync(0xffffffff, az, off);
    }
    if (lane == 0) {
        float invn = 1.0f / (256.0f + 1e-6f);
        float* op = out + (b*Nc + i)*3;
        op[0] = cx + ax*invn;
        op[1] = cy + ay*invn;
        op[2] = cz + az*invn;
    }
}

// ---------------- energy head ----------------
__global__ __launch_bounds__(128) void energy_kernel(const float* __restrict__ h,
                                                     const float* __restrict__ enw,
                                                     const float* __restrict__ enb,
                                                     float* __restrict__ out) {
    int b = blockIdx.x;
    int tid = threadIdx.x;
    const float* row = h + (b*Nc)*Dc;
    float s = 0.f;
    #pragma unroll
    for (int j = 0; j < 4; j++) {
        int d = tid + 128*j;
        s += row[d]*enw[d];
    }
    #pragma unroll
    for (int off = 16; off; off >>= 1)
        s += __shfl_xor_sync(0xffffffff, s, off);
    __shared__ float rs[4];
    int wid = tid >> 5, lane = tid & 31;
    if (lane == 0) rs[wid] = s;
    __syncthreads();
    if (tid == 0)
        out[Bc*Nc*3 + b] = rs[0]+rs[1]+rs[2]+rs[3] + enb[0];
}

// ---------------- host ----------------
extern "C" void kernel_launch(void* const* d_in, const int* in_sizes, int n_in,
                              void* d_out, int out_size) {
    bool has_mask = (n_in >= 31);
    auto IN = [&](int i) -> const void* {
        int k = i;
        if (!has_mask && i > 3) k = i - 1;
        return d_in[k];
    };
    const int*   atom_types = (const int*)  IN(0);
    const float* coords     = (const float*)IN(1);
    const int*   pair_types = (const int*)  IN(2);
    const float* atom_emb   = (const float*)IN(4);
    const float* gmu        = (const float*)IN(5);
    const float* gsigma     = (const float*)IN(6);
    const float* pair_a     = (const float*)IN(7);
    const float* pair_b     = (const float*)IN(8);
    const float* pl_w       = (const float*)IN(9);
    const float* pl_b       = (const float*)IN(10);
    const float* ln1_g      = (const float*)IN(11);
    const float* ln1_b      = (const float*)IN(12);
    const float* qkv_w      = (const float*)IN(13);
    const float* qkv_b      = (const float*)IN(14);
    const float* pp_w       = (const float*)IN(15);
    const float* pp_b       = (const float*)IN(16);
    const float* out_w      = (const float*)IN(17);
    const float* out_b      = (const float*)IN(18);
    const float* ln2_g      = (const float*)IN(19);
    const float* ln2_b      = (const float*)IN(20);
    const float* ffn_w1     = (const float*)IN(21);
    const float* ffn_b1     = (const float*)IN(22);
    const float* ffn_w2     = (const float*)IN(23);
    const float* ffn_b2     = (const float*)IN(24);
    const float* se3_uw     = (const float*)IN(25);
    const float* se3_ub     = (const float*)IN(26);
    const float* se3_ww     = (const float*)IN(27);
    const float* se3_wb     = (const float*)IN(28);
    const float* en_w       = (const float*)IN(29);
    const float* en_b       = (const float*)IN(30);
    float* out = (float*)d_out;

    float *hb, *qkvb, *pairb, *splitb;
    __half *x16, *a16, *f16, *wh;
    cudaGetSymbolAddress((void**)&hb,     g_h);
    cudaGetSymbolAddress((void**)&qkvb,   g_qkv);
    cudaGetSymbolAddress((void**)&pairb,  g_pair);
    cudaGetSymbolAddress((void**)&splitb, g_split);
    cudaGetSymbolAddress((void**)&x16, g_x16);
    cudaGetSymbolAddress((void**)&a16, g_a16);
    cudaGetSymbolAddress((void**)&f16, g_f16);
    cudaGetSymbolAddress((void**)&wh,  g_wh);

    cudaFuncSetAttribute(gemm_fp16_kernel,
                         cudaFuncAttributeMaxDynamicSharedMemorySize, SMEM_DYN);

    // convert all weights to fp16 (once per call)
    wconv_kernel<<<(11796480/4 + 255)/256, 256>>>(qkv_w,  wh + QKVB, 11796480/4);
    wconv_kernel<<<( 3932160/4 + 255)/256, 256>>>(out_w,  wh + OUTB,  3932160/4);
    wconv_kernel<<<(15728640/4 + 255)/256, 256>>>(ffn_w1, wh + F1B,  15728640/4);
    wconv_kernel<<<(15728640/4 + 255)/256, 256>>>(ffn_w2, wh + F2B,  15728640/4);

    tab_kernel<<<(TABN + 256)/256, 256>>>(gmu, gsigma, pl_w, pl_b);
    emb_kernel<<<(Mc*Dc + 255)/256, 256>>>(atom_types, atom_emb, hb);
    pair_kernel<<<(Bc*Nc*Nc)/256, 256>>>(coords, pair_types, pair_a, pair_b, pairb);

    for (int l = 0; l < Lc; l++) {
        const float* qb  = qkv_b + l*3*Dc;
        const float* pwp = pp_w + l*Hc;
        const float* pbp = pp_b + l*Hc;
        const float* ob  = out_b + l*Dc;
        const float* l2g = ln2_g + l*Dc;
        const float* l2b = ln2_b + l*Dc;
        const float* b1  = ffn_b1 + l*Fc;
        const float* b2  = ffn_b2 + l*Dc;
        const __half* qw = wh + QKVB + (size_t)l*786432;
        const __half* ow = wh + OUTB + (size_t)l*262144;
        const __half* w1 = wh + F1B  + (size_t)l*1048576;
        const __half* w2 = wh + F2B  + (size_t)l*1048576;

        if (l == 0)
            ln_kernel<<<Mc, 128>>>(hb, ln1_g, ln1_b, x16);
        gemm_fp16_kernel<<<dim3((3*Dc)/BN, Mc/BM, 1), 256, SMEM_DYN>>>(
            x16, qw, nullptr, qkvb, nullptr, Mc, 3*Dc, Dc, 0);
        attn_kernel<<<dim3(Bc*Hc, 4), 256>>>(qkvb, qb, pairb, pwp, pbp, a16);
        gemm_fp16_kernel<<<dim3(Dc/BN, Mc/BM, SPLITK), 256, SMEM_DYN>>>(
            a16, ow, nullptr, splitb, nullptr, Mc, Dc, Dc, 0);
        reduce_ln_kernel<<<Mc, 128>>>(splitb, ob, hb, l2g, l2b, x16);
        gemm_fp16_kernel<<<dim3(Fc/BN, Mc/BM, 1), 256, SMEM_DYN>>>(
            x16, w1, b1, nullptr, f16, Mc, Fc, Dc, 1);
        gemm_fp16_kernel<<<dim3(Dc/BN, Mc/BM, SPLITK), 256, SMEM_DYN>>>(
            f16, w2, nullptr, splitb, nullptr, Mc, Dc, Fc, 0);
        if (l < Lc-1) {
            reduce_ln_kernel<<<Mc, 128>>>(splitb, b2, hb,
                                          ln1_g + (l+1)*Dc, ln1_b + (l+1)*Dc, x16);
        } else {
            reduce_splitk<<<(Mc*Dc/4 + 255)/256, 256>>>(splitb, b2, hb, Mc*Dc, Dc);
        }
    }

    coords_kernel<<<(Bc*Nc)/4, 128>>>(coords, pairb, se3_uw, se3_ub, se3_ww, se3_wb, out);
    energy_kernel<<<Bc, 128>>>(hb, en_w, en_b, out);
    (void)in_sizes; (void)out_size;
}

// round 16
// speedup vs baseline: 1.6233x; 1.0314x over previous
#include <cuda_runtime.h>
#include <cuda_fp16.h>
#include <mma.h>
#include <math.h>
#include <cstdint>
#include <stdint.h>

using namespace nvcuda;

// Problem constants
#define Lc 15
#define Dc 512
#define Hc 64
#define HDc 8
#define Fc 2048
#define Gc 128
#define Bc 4
#define Nc 256
#define Mc (Bc*Nc)   // 1024 rows
#define SPLITK 4
#define TABN 8192

// Weight region bases (elements) inside g_wh
#define QKVB 0
#define OUTB 11796480
#define F1B  15728640
#define F2B  31457280
#define WTOT 47185920

// -------- scratch (device globals; no allocation allowed) --------
__device__ float g_h[Mc*Dc];
__device__ float g_qkv[Mc*3*Dc];
__device__ float g_pair[Bc*Nc*Nc];
__device__ float g_split[SPLITK*Mc*Dc];
__device__ float g_tab[TABN+1];
__device__ __half g_x16[Mc*Dc];     // LN outputs (fp16)
__device__ __half g_a16[Mc*Dc];     // attention outputs (fp16)
__device__ __half g_f16[Mc*Fc];     // FFN1/gelu outputs (fp16)
__device__ __half g_wh[WTOT];

// ---------------- gaussian table build ----------------
__global__ void tab_kernel(const float* __restrict__ mu,
                           const float* __restrict__ sigma,
                           const float* __restrict__ plw,
                           const float* __restrict__ plb) {
    int i = blockIdx.x*256 + threadIdx.x;
    if (i > TABN) return;
    float da = -8.0f + (float)i * (1.0f/512.0f);
    float s = 0.f;
    #pragma unroll 8
    for (int g = 0; g < Gc; g++) {
        float sg = sigma[g];
        float coef = plw[g] / (2.0f*sg*sg) / (sg * 2.5066282746310002f);
        float t = da - mu[g];
        s += __expf(-t*t) * coef;
    }
    g_tab[i] = s + plb[0];
}

// ---------------- pair representation via table lookup ----------------
__global__ void pair_kernel(const float* __restrict__ coords,
                            const int* __restrict__ ptypes,
                            const float* __restrict__ pa,
                            const float* __restrict__ pb,
                            float* __restrict__ pr) {
    int p = blockIdx.x * blockDim.x + threadIdx.x;
    int b = p >> 16;
    int rem = p & 65535;
    int i = rem >> 8, j = rem & 255;
    const float* ci = coords + (b*Nc + i)*3;
    const float* cj = coords + (b*Nc + j)*3;
    float dx = ci[0]-cj[0], dy = ci[1]-cj[1], dz = ci[2]-cj[2];
    float d2 = dx*dx + dy*dy + dz*dz;
    float dist = sqrtf(fmaxf(d2, 1e-12f));
    int pt = ptypes[p];
    float da = pa[pt]*dist + pb[pt];
    float t = (da + 8.0f) * 512.0f;
    t = fminf(fmaxf(t, 0.0f), (float)(TABN - 1));
    int idx = (int)t;
    float fr = t - (float)idx;
    float f0 = g_tab[idx], f1 = g_tab[idx+1];
    pr[p] = f0 + fr*(f1 - f0);
}

// ---------------- weight convert: fp32 -> fp16 (RNE) ----------------
__global__ void wconv_kernel(const float* __restrict__ src,
                             __half* __restrict__ dh, int n4) {
    int i = blockIdx.x*256 + threadIdx.x;
    if (i >= n4) return;
    float4 v = ((const float4*)src)[i];
    ((__half2*)dh)[i*2]   = __halves2half2(__float2half_rn(v.x), __float2half_rn(v.y));
    ((__half2*)dh)[i*2+1] = __halves2half2(__float2half_rn(v.z), __float2half_rn(v.w));
}

// ---------------- embedding ----------------
__global__ void emb_kernel(const int* __restrict__ atom_types,
                           const float* __restrict__ atom_emb,
                           float* __restrict__ h) {
    int idx = blockIdx.x * blockDim.x + threadIdx.x;
    if (idx >= Mc*Dc) return;
    int row = idx >> 9;
    int d   = idx & 511;
    h[idx] = atom_emb[atom_types[row]*Dc + d];
}

// ---------------- layernorm: warp-per-row, no barriers ----------------
__global__ __launch_bounds__(256) void ln_kernel(const float* __restrict__ in,
                                                 const float* __restrict__ g,
                                                 const float* __restrict__ bb,
                                                 __half* __restrict__ out) {
    int row = blockIdx.x*8 + (threadIdx.x >> 5);
    int lane = threadIdx.x & 31;
    const float* x = in + row*Dc;
    float v[16], s = 0.f, s2 = 0.f;
    #pragma unroll
    for (int j = 0; j < 16; j++) {
        v[j] = x[lane + 32*j];
        s += v[j]; s2 += v[j]*v[j];
    }
    #pragma unroll
    for (int off = 16; off; off >>= 1) {
        s  += __shfl_xor_sync(0xffffffff, s,  off);
        s2 += __shfl_xor_sync(0xffffffff, s2, off);
    }
    float mean = s * (1.0f/Dc);
    float var  = s2 * (1.0f/Dc) - mean*mean;
    float rstd = rsqrtf(var + 1e-5f);
    #pragma unroll
    for (int j = 0; j < 16; j++) {
        int d = lane + 32*j;
        out[row*Dc + d] = __float2half_rn((v[j]-mean)*rstd*g[d] + bb[d]);
    }
}

// ---------------- fused split-K reduce + layernorm (warp-per-row) ----------------
__global__ __launch_bounds__(256) void reduce_ln_kernel(
    const float* __restrict__ P, const float* __restrict__ bias,
    float* __restrict__ h, const float* __restrict__ g,
    const float* __restrict__ bb, __half* __restrict__ xout) {
    int row = blockIdx.x*8 + (threadIdx.x >> 5);
    int lane = threadIdx.x & 31;
    const int MN = Mc*Dc;
    float v[16], s = 0.f, s2 = 0.f;
    #pragma unroll
    for (int j = 0; j < 16; j++) {
        int d = lane + 32*j;
        int idx = row*Dc + d;
        float val = h[idx] + bias[d]
                  + P[idx] + P[idx + MN] + P[idx + 2*MN] + P[idx + 3*MN];
        h[idx] = val;
        v[j] = val; s += val; s2 += val*val;
    }
    #pragma unroll
    for (int off = 16; off; off >>= 1) {
        s  += __shfl_xor_sync(0xffffffff, s,  off);
        s2 += __shfl_xor_sync(0xffffffff, s2, off);
    }
    float mean = s * (1.0f/Dc);
    float var  = s2 * (1.0f/Dc) - mean*mean;
    float rstd = rsqrtf(var + 1e-5f);
    #pragma unroll
    for (int j = 0; j < 16; j++) {
        int d = lane + 32*j;
        xout[row*Dc + d] = __float2half_rn((v[j]-mean)*rstd*g[d] + bb[d]);
    }
}

// ---------------- plain split-K reduce (final layer) ----------------
__global__ __launch_bounds__(256) void reduce_splitk(const float* __restrict__ P,
                                                     const float* __restrict__ bias,
                                                     float* __restrict__ h,
                                                     int MN, int N) {
    int i4 = blockIdx.x*256 + threadIdx.x;
    if (i4 >= MN/4) return;
    int n = (i4*4) & (N-1);
    const float4* P4 = (const float4*)P;
    int stride4 = MN/4;
    float4 s0 = P4[i4];
    float4 s1 = P4[i4 + stride4];
    float4 s2 = P4[i4 + 2*stride4];
    float4 s3 = P4[i4 + 3*stride4];
    float4 b  = *(const float4*)(bias + n);
    float4 hv = ((float4*)h)[i4];
    hv.x += s0.x + s1.x + s2.x + s3.x + b.x;
    hv.y += s0.y + s1.y + s2.y + s3.y + b.y;
    hv.z += s0.z + s1.z + s2.z + s3.z + b.z;
    hv.w += s0.w + s1.w + s2.w + s3.w + b.w;
    ((float4*)h)[i4] = hv;
}

// ---------------- pure fp16 GEMM: D = A*W^T, fp32 acc, BK=64 ----------------
// A, W: fp16 (RNE-rounded). direct (bias==null && oh==null): raw fp32 frag
// stores (+z*M*N if split-K). staged: +bias [,gelu]; oh -> fp16 out; else fp32 C.
#define BM 128
#define BN 64
#define BKT 64
#define LDA 72
#define LDC 68
#define SBUF 27648           // A 128*72*2 + W 64*72*2
#define SMEM_DYN 55296       // max(2*SBUF, epilogue 128*68*4 = 34816)
__global__ __launch_bounds__(256, 2) void gemm_fp16_kernel(
    const __half* __restrict__ A, const __half* __restrict__ Wg,
    const float* __restrict__ bias,
    float* __restrict__ C, __half* __restrict__ oh,
    int M, int N, int K, int act)
{
    extern __shared__ __align__(16) char smem[];
    int tid = threadIdx.x;
    int m0 = blockIdx.y*BM, n0 = blockIdx.x*BN;
    int S = gridDim.z;
    int Ks = K / S;
    int kbeg = blockIdx.z * Ks;

    int wid = tid >> 5;
    int wm = (wid >> 1) * 32;
    int wn = (wid & 1) * 32;

    // staging: tile rows of 64 halves = 8 uint4. A: 1024 uint4 (4/thr), W: 512 (2/thr)
    int ar = tid >> 3, ac = (tid & 7) * 8;
    const __half* pA0 = A  + (size_t)(m0+ar)*K + kbeg + ac;      // rows 0..31
    const __half* pW  = Wg + (size_t)(n0+ar)*K + kbeg + ac;      // rows 0..31
    unsigned offA = (unsigned)(ar*LDA + ac);

    wmma::fragment<wmma::accumulator, 16, 16, 16, float> acc[2][2];
    #pragma unroll
    for (int i = 0; i < 2; i++)
        #pragma unroll
        for (int j = 0; j < 2; j++)
            wmma::fill_fragment(acc[i][j], 0.0f);

    uint4 ra[4], rw[2];
    #pragma unroll
    for (int i = 0; i < 4; i++)
        ra[i] = *(const uint4*)(pA0 + (size_t)(i*32)*K);
    #pragma unroll
    for (int i = 0; i < 2; i++)
        rw[i] = *(const uint4*)(pW + (size_t)(i*32)*K);

    int nt = Ks / BKT;
    for (int t = 0; t < nt; t++) {
        char* buf = smem + (t & 1)*SBUF;
        __half* As = (__half*)buf;
        __half* Ws = As + BM*LDA;

        #pragma unroll
        for (int i = 0; i < 4; i++)
            *(uint4*)&As[offA + i*32*LDA] = ra[i];
        #pragma unroll
        for (int i = 0; i < 2; i++)
            *(uint4*)&Ws[offA + i*32*LDA] = rw[i];

        if (t + 1 < nt) {
            int k0 = (t+1)*BKT;
            #pragma unroll
            for (int i = 0; i < 4; i++)
                ra[i] = *(const uint4*)(pA0 + (size_t)(i*32)*K + k0);
            #pragma unroll
            for (int i = 0; i < 2; i++)
                rw[i] = *(const uint4*)(pW + (size_t)(i*32)*K + k0);
        }

        __syncthreads();   // the ONLY barrier per tile

        #pragma unroll
        for (int ks = 0; ks < BKT; ks += 16) {
            wmma::fragment<wmma::matrix_a, 16, 16, 16, __half, wmma::row_major> af[2];
            wmma::fragment<wmma::matrix_b, 16, 16, 16, __half, wmma::col_major> bf[2];
            #pragma unroll
            for (int i = 0; i < 2; i++)
                wmma::load_matrix_sync(af[i], As + (wm + i*16)*LDA + ks, LDA);
            #pragma unroll
            for (int j = 0; j < 2; j++)
                wmma::load_matrix_sync(bf[j], Ws + (wn + j*16)*LDA + ks, LDA);
            #pragma unroll
            for (int i = 0; i < 2; i++)
                #pragma unroll
                for (int j = 0; j < 2; j++)
                    wmma::mma_sync(acc[i][j], af[i], bf[j], acc[i][j]);
        }
        // no trailing sync: next iter writes the other buffer
    }

    if (bias == nullptr && oh == nullptr) {
        float* Cp = C + (size_t)blockIdx.z*M*N;
        #pragma unroll
        for (int i = 0; i < 2; i++)
            #pragma unroll
            for (int j = 0; j < 2; j++)
                wmma::store_matrix_sync(Cp + (size_t)(m0+wm+i*16)*N + n0+wn+j*16,
                                        acc[i][j], N, wmma::mem_row_major);
        return;
    }

    __syncthreads();
    float* Ct = (float*)smem;   // 128*68*4 = 34816 <= SMEM_DYN
    #pragma unroll
    for (int i = 0; i < 2; i++)
        #pragma unroll
        for (int j = 0; j < 2; j++)
            wmma::store_matrix_sync(Ct + (wm+i*16)*LDC + wn+j*16,
                                    acc[i][j], LDC, wmma::mem_row_major);
    __syncthreads();

    int col = (tid & 15) * 4;
    int r0  = tid >> 4;
    float4 bv = *(const float4*)(bias + n0 + col);
    #pragma unroll
    for (int rr = 0; rr < 8; rr++) {
        int row = rr*16 + r0;
        float vr[4];
        *(float4*)vr = *(const float4*)&Ct[row*LDC + col];
        vr[0] += bv.x; vr[1] += bv.y; vr[2] += bv.z; vr[3] += bv.w;
        if (act == 1) {
            #pragma unroll
            for (int j = 0; j < 4; j++)
                vr[j] = 0.5f * vr[j] * (1.0f + erff(vr[j] * 0.7071067811865475f));
        }
        size_t base = (size_t)(m0+row)*N + n0 + col;
        if (oh) {
            __half2 p0 = __halves2half2(__float2half_rn(vr[0]), __float2half_rn(vr[1]));
            __half2 p1 = __halves2half2(__float2half_rn(vr[2]), __float2half_rn(vr[3]));
            *(__half2*)&oh[base]   = p0;
            *(__half2*)&oh[base+2] = p1;
        } else {
            *(float4*)(C + base) = *(float4*)vr;
        }
    }
}

// ---------------- fused attention (QKV bias + scores + softmax + PV) ----------------
__global__ __launch_bounds__(256) void attn_kernel(const float* __restrict__ qkv,
                                                   const float* __restrict__ qb,
                                                   const float* __restrict__ pr,
                                                   const float* __restrict__ ppw,
                                                   const float* __restrict__ ppb,
                                                   __half* __restrict__ out) {
    int b = blockIdx.x >> 6;
    int h = blockIdx.x & 63;
    __shared__ float Ks[Nc*9];
    __shared__ float Vs[Nc*9];
    int tid = threadIdx.x;
    float4 bq0 = *(const float4*)(qb + h*HDc);
    float4 bq1 = *(const float4*)(qb + h*HDc + 4);
    float4 bk0 = *(const float4*)(qb + Dc + h*HDc);
    float4 bk1 = *(const float4*)(qb + Dc + h*HDc + 4);
    float4 bv0 = *(const float4*)(qb + 2*Dc + h*HDc);
    float4 bv1 = *(const float4*)(qb + 2*Dc + h*HDc + 4);
    {
        int n = tid;
        const float* kp = qkv + (((b*Nc + n)*3 + 1))*Dc + h*HDc;
        const float* vp = kp + Dc;
        float4 k0 = *(const float4*)kp,     k1 = *(const float4*)(kp+4);
        float4 v0 = *(const float4*)vp,     v1 = *(const float4*)(vp+4);
        float* kd = &Ks[n*9];
        kd[0]=k0.x+bk0.x; kd[1]=k0.y+bk0.y; kd[2]=k0.z+bk0.z; kd[3]=k0.w+bk0.w;
        kd[4]=k1.x+bk1.x; kd[5]=k1.y+bk1.y; kd[6]=k1.z+bk1.z; kd[7]=k1.w+bk1.w;
        float* vd = &Vs[n*9];
        vd[0]=v0.x+bv0.x; vd[1]=v0.y+bv0.y; vd[2]=v0.z+bv0.z; vd[3]=v0.w+bv0.w;
        vd[4]=v1.x+bv1.x; vd[5]=v1.y+bv1.y; vd[6]=v1.z+bv1.z; vd[7]=v1.w+bv1.w;
    }
    __syncthreads();
    const float scale = 0.3535533905932738f;
    float pw = ppw[h], pb = ppb[h];
    int warp = tid >> 5, lane = tid & 31;
    #pragma unroll
    for (int r = 0; r < 8; r++) {
        int i = blockIdx.y*64 + warp*8 + r;
        const float* qp = qkv + ((b*Nc + i)*3)*Dc + h*HDc;
        float4 q0 = *(const float4*)qp, q1 = *(const float4*)(qp+4);
        float qr[8];
        qr[0]=q0.x+bq0.x; qr[1]=q0.y+bq0.y; qr[2]=q0.z+bq0.z; qr[3]=q0.w+bq0.w;
        qr[4]=q1.x+bq1.x; qr[5]=q1.y+bq1.y; qr[6]=q1.z+bq1.z; qr[7]=q1.w+bq1.w;
        const float* prow = pr + (b*Nc + i)*Nc;
        float s[8];
        float mx = -1e30f;
        #pragma unroll
        for (int jj = 0; jj < 8; jj++) {
            int j = lane + 32*jj;
            const float* kk = &Ks[j*9];
            float d = qr[0]*kk[0] + qr[1]*kk[1] + qr[2]*kk[2] + qr[3]*kk[3]
                    + qr[4]*kk[4] + qr[5]*kk[5] + qr[6]*kk[6] + qr[7]*kk[7];
            s[jj] = d*scale + prow[j]*pw + pb;
            mx = fmaxf(mx, s[jj]);
        }
        #pragma unroll
        for (int off = 16; off; off >>= 1)
            mx = fmaxf(mx, __shfl_xor_sync(0xffffffff, mx, off));
        float sum = 0.f;
        #pragma unroll
        for (int jj = 0; jj < 8; jj++) { s[jj] = __expf(s[jj]-mx); sum += s[jj]; }
        #pragma unroll
        for (int off = 16; off; off >>= 1)
            sum += __shfl_xor_sync(0xffffffff, sum, off);
        float inv = 1.0f / sum;
        float acc[8] = {};
        #pragma unroll
        for (int jj = 0; jj < 8; jj++) {
            int j = lane + 32*jj;
            float p = s[jj]*inv;
            const float* vv = &Vs[j*9];
            #pragma unroll
            for (int d = 0; d < 8; d++) acc[d] += p*vv[d];
        }
        #pragma unroll
        for (int off = 16; off; off >>= 1) {
            #pragma unroll
            for (int d = 0; d < 8; d++)
                acc[d] += __shfl_xor_sync(0xffffffff, acc[d], off);
        }
        if (lane == 0) {
            __half* op = out + (size_t)(b*Nc + i)*Dc + h*HDc;
            #pragma unroll
            for (int d = 0; d < 8; d++) op[d] = __float2half_rn(acc[d]);
        }
    }
}

// ---------------- SE(3) coordinate update ----------------
__global__ __launch_bounds__(128) void coords_kernel(const float* __restrict__ coords,
                                                     const float* __restrict__ pr,
                                                     const float* __restrict__ uw,
                                                     const float* __restrict__ ub,
                                                     const float* __restrict__ ww,
                                                     const float* __restrict__ wb,
                                                     float* __restrict__ out) {
    int gw = blockIdx.x * 4 + (threadIdx.x >> 5);
    int lane = threadIdx.x & 31;
    int b = gw >> 8, i = gw & 255;
    float u0 = uw[0], u1 = ub[0], w0 = ww[0], w1 = wb[0];
    const float* ci = coords + (b*Nc + i)*3;
    float cx = ci[0], cy = ci[1], cz = ci[2];
    float ax = 0.f, ay = 0.f, az = 0.f;
    const float* prow = pr + (b*Nc + i)*Nc;
    #pragma unroll
    for (int jj = 0; jj < 8; jj++) {
        int j = lane + 32*jj;
        const float* cj = coords + (b*Nc + j)*3;
        float c = (fmaxf(prow[j], 0.f)*u0 + u1)*w0 + w1;
        ax += (cx - cj[0])*c;
        ay += (cy - cj[1])*c;
        az += (cz - cj[2])*c;
    }
    #pragma unroll
    for (int off = 16; off; off >>= 1) {
        ax += __shfl_xor_sync(0xffffffff, ax, off);
        ay += __shfl_xor_sync(0xffffffff, ay, off);
        az += __shfl_xor_sync(0xffffffff, az, off);
    }
    if (lane == 0) {
        float invn = 1.0f / (256.0f + 1e-6f);
        float* op = out + (b*Nc + i)*3;
        op[0] = cx + ax*invn;
        op[1] = cy + ay*invn;
        op[2] = cz + az*invn;
    }
}

// ---------------- energy head ----------------
__global__ __launch_bounds__(128) void energy_kernel(const float* __restrict__ h,
                                                     const float* __restrict__ enw,
                                                     const float* __restrict__ enb,
                                                     float* __restrict__ out) {
    int b = blockIdx.x;
    int tid = threadIdx.x;
    const float* row = h + (b*Nc)*Dc;
    float s = 0.f;
    #pragma unroll
    for (int j = 0; j < 4; j++) {
        int d = tid + 128*j;
        s += row[d]*enw[d];
    }
    #pragma unroll
    for (int off = 16; off; off >>= 1)
        s += __shfl_xor_sync(0xffffffff, s, off);
    __shared__ float rs[4];
    int wid = tid >> 5, lane = tid & 31;
    if (lane == 0) rs[wid] = s;
    __syncthreads();
    if (tid == 0)
        out[Bc*Nc*3 + b] = rs[0]+rs[1]+rs[2]+rs[3] + enb[0];
}

// ---------------- host ----------------
extern "C" void kernel_launch(void* const* d_in, const int* in_sizes, int n_in,
                              void* d_out, int out_size) {
    bool has_mask = (n_in >= 31);
    auto IN = [&](int i) -> const void* {
        int k = i;
        if (!has_mask && i > 3) k = i - 1;
        return d_in[k];
    };
    const int*   atom_types = (const int*)  IN(0);
    const float* coords     = (const float*)IN(1);
    const int*   pair_types = (const int*)  IN(2);
    const float* atom_emb   = (const float*)IN(4);
    const float* gmu        = (const float*)IN(5);
    const float* gsigma     = (const float*)IN(6);
    const float* pair_a     = (const float*)IN(7);
    const float* pair_b     = (const float*)IN(8);
    const float* pl_w       = (const float*)IN(9);
    const float* pl_b       = (const float*)IN(10);
    const float* ln1_g      = (const float*)IN(11);
    const float* ln1_b      = (const float*)IN(12);
    const float* qkv_w      = (const float*)IN(13);
    const float* qkv_b      = (const float*)IN(14);
    const float* pp_w       = (const float*)IN(15);
    const float* pp_b       = (const float*)IN(16);
    const float* out_w      = (const float*)IN(17);
    const float* out_b      = (const float*)IN(18);
    const float* ln2_g      = (const float*)IN(19);
    const float* ln2_b      = (const float*)IN(20);
    const float* ffn_w1     = (const float*)IN(21);
    const float* ffn_b1     = (const float*)IN(22);
    const float* ffn_w2     = (const float*)IN(23);
    const float* ffn_b2     = (const float*)IN(24);
    const float* se3_uw     = (const float*)IN(25);
    const float* se3_ub     = (const float*)IN(26);
    const float* se3_ww     = (const float*)IN(27);
    const float* se3_wb     = (const float*)IN(28);
    const float* en_w       = (const float*)IN(29);
    const float* en_b       = (const float*)IN(30);
    float* out = (float*)d_out;

    float *hb, *qkvb, *pairb, *splitb;
    __half *x16, *a16, *f16, *wh;
    cudaGetSymbolAddress((void**)&hb,     g_h);
    cudaGetSymbolAddress((void**)&qkvb,   g_qkv);
    cudaGetSymbolAddress((void**)&pairb,  g_pair);
    cudaGetSymbolAddress((void**)&splitb, g_split);
    cudaGetSymbolAddress((void**)&x16, g_x16);
    cudaGetSymbolAddress((void**)&a16, g_a16);
    cudaGetSymbolAddress((void**)&f16, g_f16);
    cudaGetSymbolAddress((void**)&wh,  g_wh);

    cudaFuncSetAttribute(gemm_fp16_kernel,
                         cudaFuncAttributeMaxDynamicSharedMemorySize, SMEM_DYN);

    // convert all weights to fp16 (once per call)
    wconv_kernel<<<(11796480/4 + 255)/256, 256>>>(qkv_w,  wh + QKVB, 11796480/4);
    wconv_kernel<<<( 3932160/4 + 255)/256, 256>>>(out_w,  wh + OUTB,  3932160/4);
    wconv_kernel<<<(15728640/4 + 255)/256, 256>>>(ffn_w1, wh + F1B,  15728640/4);
    wconv_kernel<<<(15728640/4 + 255)/256, 256>>>(ffn_w2, wh + F2B,  15728640/4);

    tab_kernel<<<(TABN + 256)/256, 256>>>(gmu, gsigma, pl_w, pl_b);
    emb_kernel<<<(Mc*Dc + 255)/256, 256>>>(atom_types, atom_emb, hb);
    pair_kernel<<<(Bc*Nc*Nc)/256, 256>>>(coords, pair_types, pair_a, pair_b, pairb);

    for (int l = 0; l < Lc; l++) {
        const float* qb  = qkv_b + l*3*Dc;
        const float* pwp = pp_w + l*Hc;
        const float* pbp = pp_b + l*Hc;
        const float* ob  = out_b + l*Dc;
        const float* l2g = ln2_g + l*Dc;
        const float* l2b = ln2_b + l*Dc;
        const float* b1  = ffn_b1 + l*Fc;
        const float* b2  = ffn_b2 + l*Dc;
        const __half* qw = wh + QKVB + (size_t)l*786432;
        const __half* ow = wh + OUTB + (size_t)l*262144;
        const __half* w1 = wh + F1B  + (size_t)l*1048576;
        const __half* w2 = wh + F2B  + (size_t)l*1048576;

        if (l == 0)
            ln_kernel<<<Mc/8, 256>>>(hb, ln1_g, ln1_b, x16);
        gemm_fp16_kernel<<<dim3((3*Dc)/BN, Mc/BM, 1), 256, SMEM_DYN>>>(
            x16, qw, nullptr, qkvb, nullptr, Mc, 3*Dc, Dc, 0);
        attn_kernel<<<dim3(Bc*Hc, 4), 256>>>(qkvb, qb, pairb, pwp, pbp, a16);
        gemm_fp16_kernel<<<dim3(Dc/BN, Mc/BM, SPLITK), 256, SMEM_DYN>>>(
            a16, ow, nullptr, splitb, nullptr, Mc, Dc, Dc, 0);
        reduce_ln_kernel<<<Mc/8, 256>>>(splitb, ob, hb, l2g, l2b, x16);
        gemm_fp16_kernel<<<dim3(Fc/BN, Mc/BM, 1), 256, SMEM_DYN>>>(
            x16, w1, b1, nullptr, f16, Mc, Fc, Dc, 1);
        gemm_fp16_kernel<<<dim3(Dc/BN, Mc/BM, SPLITK), 256, SMEM_DYN>>>(
            f16, w2, nullptr, splitb, nullptr, Mc, Dc, Fc, 0);
        if (l < Lc-1) {
            reduce_ln_kernel<<<Mc/8, 256>>>(splitb, b2, hb,
                                            ln1_g + (l+1)*Dc, ln1_b + (l+1)*Dc, x16);
        } else {
            reduce_splitk<<<(Mc*Dc/4 + 255)/256, 256>>>(splitb, b2, hb, Mc*Dc, Dc);
        }
    }

    coords_kernel<<<(Bc*Nc)/4, 128>>>(coords, pairb, se3_uw, se3_ub, se3_ww, se3_wb, out);
    energy_kernel<<<Bc, 128>>>(hb, en_w, en_b, out);
    (void)in_sizes; (void)out_size;
}

// round 17
// speedup vs baseline: 1.6271x; 1.0023x over previous
#include <cuda_runtime.h>
#include <cuda_fp16.h>
#include <mma.h>
#include <math.h>
#include <cstdint>
#include <stdint.h>

using namespace nvcuda;

// Problem constants
#define Lc 15
#define Dc 512
#define Hc 64
#define HDc 8
#define Fc 2048
#define Gc 128
#define Bc 4
#define Nc 256
#define Mc (Bc*Nc)   // 1024 rows
#define SPLITK 4
#define TABN 8192

// Weight region bases (elements) inside g_wh
#define QKVB 0
#define OUTB 11796480
#define F1B  15728640
#define F2B  31457280
#define WTOT 47185920

// -------- scratch (device globals; no allocation allowed) --------
__device__ float g_h[Mc*Dc];
__device__ float g_qkv[Mc*3*Dc];
__device__ float g_pair[Bc*Nc*Nc];
__device__ float g_split[SPLITK*Mc*Dc];
__device__ float g_tab[TABN+1];
__device__ __half g_x16[Mc*Dc];
__device__ __half g_a16[Mc*Dc];
__device__ __half g_f16[Mc*Fc];
__device__ __half g_wh[WTOT];

// ---------------- gaussian table build ----------------
__global__ void tab_kernel(const float* __restrict__ mu,
                           const float* __restrict__ sigma,
                           const float* __restrict__ plw,
                           const float* __restrict__ plb) {
    int i = blockIdx.x*256 + threadIdx.x;
    if (i > TABN) return;
    float da = -8.0f + (float)i * (1.0f/512.0f);
    float s = 0.f;
    #pragma unroll 8
    for (int g = 0; g < Gc; g++) {
        float sg = sigma[g];
        float coef = plw[g] / (2.0f*sg*sg) / (sg * 2.5066282746310002f);
        float t = da - mu[g];
        s += __expf(-t*t) * coef;
    }
    g_tab[i] = s + plb[0];
}

// ---------------- pair representation via table lookup ----------------
__global__ void pair_kernel(const float* __restrict__ coords,
                            const int* __restrict__ ptypes,
                            const float* __restrict__ pa,
                            const float* __restrict__ pb,
                            float* __restrict__ pr) {
    int p = blockIdx.x * blockDim.x + threadIdx.x;
    int b = p >> 16;
    int rem = p & 65535;
    int i = rem >> 8, j = rem & 255;
    const float* ci = coords + (b*Nc + i)*3;
    const float* cj = coords + (b*Nc + j)*3;
    float dx = ci[0]-cj[0], dy = ci[1]-cj[1], dz = ci[2]-cj[2];
    float d2 = dx*dx + dy*dy + dz*dz;
    float dist = sqrtf(fmaxf(d2, 1e-12f));
    int pt = ptypes[p];
    float da = pa[pt]*dist + pb[pt];
    float t = (da + 8.0f) * 512.0f;
    t = fminf(fmaxf(t, 0.0f), (float)(TABN - 1));
    int idx = (int)t;
    float fr = t - (float)idx;
    float f0 = g_tab[idx], f1 = g_tab[idx+1];
    pr[p] = f0 + fr*(f1 - f0);
}

// ---------------- weight convert: fp32 -> fp16 (RNE) ----------------
__global__ void wconv_kernel(const float* __restrict__ src,
                             __half* __restrict__ dh, int n4) {
    int i = blockIdx.x*256 + threadIdx.x;
    if (i >= n4) return;
    float4 v = ((const float4*)src)[i];
    ((__half2*)dh)[i*2]   = __halves2half2(__float2half_rn(v.x), __float2half_rn(v.y));
    ((__half2*)dh)[i*2+1] = __halves2half2(__float2half_rn(v.z), __float2half_rn(v.w));
}

// ---------------- embedding ----------------
__global__ void emb_kernel(const int* __restrict__ atom_types,
                           const float* __restrict__ atom_emb,
                           float* __restrict__ h) {
    int idx = blockIdx.x * blockDim.x + threadIdx.x;
    if (idx >= Mc*Dc) return;
    int row = idx >> 9;
    int d   = idx & 511;
    h[idx] = atom_emb[atom_types[row]*Dc + d];
}

// ---------------- layernorm: warp-per-row ----------------
__global__ __launch_bounds__(256) void ln_kernel(const float* __restrict__ in,
                                                 const float* __restrict__ g,
                                                 const float* __restrict__ bb,
                                                 __half* __restrict__ out) {
    int row = blockIdx.x*8 + (threadIdx.x >> 5);
    int lane = threadIdx.x & 31;
    const float* x = in + row*Dc;
    float v[16], s = 0.f, s2 = 0.f;
    #pragma unroll
    for (int j = 0; j < 16; j++) {
        v[j] = x[lane + 32*j];
        s += v[j]; s2 += v[j]*v[j];
    }
    #pragma unroll
    for (int off = 16; off; off >>= 1) {
        s  += __shfl_xor_sync(0xffffffff, s,  off);
        s2 += __shfl_xor_sync(0xffffffff, s2, off);
    }
    float mean = s * (1.0f/Dc);
    float var  = s2 * (1.0f/Dc) - mean*mean;
    float rstd = rsqrtf(var + 1e-5f);
    #pragma unroll
    for (int j = 0; j < 16; j++) {
        int d = lane + 32*j;
        out[row*Dc + d] = __float2half_rn((v[j]-mean)*rstd*g[d] + bb[d]);
    }
}

// ---------------- fused split-K reduce + layernorm (warp-per-row) ----------------
__global__ __launch_bounds__(256) void reduce_ln_kernel(
    const float* __restrict__ P, const float* __restrict__ bias,
    float* __restrict__ h, const float* __restrict__ g,
    const float* __restrict__ bb, __half* __restrict__ xout) {
    int row = blockIdx.x*8 + (threadIdx.x >> 5);
    int lane = threadIdx.x & 31;
    const int MN = Mc*Dc;
    float v[16], s = 0.f, s2 = 0.f;
    #pragma unroll
    for (int j = 0; j < 16; j++) {
        int d = lane + 32*j;
        int idx = row*Dc + d;
        float val = h[idx] + bias[d]
                  + P[idx] + P[idx + MN] + P[idx + 2*MN] + P[idx + 3*MN];
        h[idx] = val;
        v[j] = val; s += val; s2 += val*val;
    }
    #pragma unroll
    for (int off = 16; off; off >>= 1) {
        s  += __shfl_xor_sync(0xffffffff, s,  off);
        s2 += __shfl_xor_sync(0xffffffff, s2, off);
    }
    float mean = s * (1.0f/Dc);
    float var  = s2 * (1.0f/Dc) - mean*mean;
    float rstd = rsqrtf(var + 1e-5f);
    #pragma unroll
    for (int j = 0; j < 16; j++) {
        int d = lane + 32*j;
        xout[row*Dc + d] = __float2half_rn((v[j]-mean)*rstd*g[d] + bb[d]);
    }
}

// ---------------- pure fp16 GEMM: D = A*W^T, fp32 acc, BK=64 ----------------
#define BM 128
#define BN 64
#define BKT 64
#define LDA 72
#define LDC 68
#define SBUF 27648
#define SMEM_DYN 55296
__global__ __launch_bounds__(256, 2) void gemm_fp16_kernel(
    const __half* __restrict__ A, const __half* __restrict__ Wg,
    const float* __restrict__ bias,
    float* __restrict__ C, __half* __restrict__ oh,
    int M, int N, int K, int act)
{
    extern __shared__ __align__(16) char smem[];
    int tid = threadIdx.x;
    int m0 = blockIdx.y*BM, n0 = blockIdx.x*BN;
    int S = gridDim.z;
    int Ks = K / S;
    int kbeg = blockIdx.z * Ks;

    int wid = tid >> 5;
    int wm = (wid >> 1) * 32;
    int wn = (wid & 1) * 32;

    int ar = tid >> 3, ac = (tid & 7) * 8;
    const __half* pA0 = A  + (size_t)(m0+ar)*K + kbeg + ac;
    const __half* pW  = Wg + (size_t)(n0+ar)*K + kbeg + ac;
    unsigned offA = (unsigned)(ar*LDA + ac);

    wmma::fragment<wmma::accumulator, 16, 16, 16, float> acc[2][2];
    #pragma unroll
    for (int i = 0; i < 2; i++)
        #pragma unroll
        for (int j = 0; j < 2; j++)
            wmma::fill_fragment(acc[i][j], 0.0f);

    uint4 ra[4], rw[2];
    #pragma unroll
    for (int i = 0; i < 4; i++)
        ra[i] = *(const uint4*)(pA0 + (size_t)(i*32)*K);
    #pragma unroll
    for (int i = 0; i < 2; i++)
        rw[i] = *(const uint4*)(pW + (size_t)(i*32)*K);

    int nt = Ks / BKT;
    for (int t = 0; t < nt; t++) {
        char* buf = smem + (t & 1)*SBUF;
        __half* As = (__half*)buf;
        __half* Ws = As + BM*LDA;

        #pragma unroll
        for (int i = 0; i < 4; i++)
            *(uint4*)&As[offA + i*32*LDA] = ra[i];
        #pragma unroll
        for (int i = 0; i < 2; i++)
            *(uint4*)&Ws[offA + i*32*LDA] = rw[i];

        if (t + 1 < nt) {
            int k0 = (t+1)*BKT;
            #pragma unroll
            for (int i = 0; i < 4; i++)
                ra[i] = *(const uint4*)(pA0 + (size_t)(i*32)*K + k0);
            #pragma unroll
            for (int i = 0; i < 2; i++)
                rw[i] = *(const uint4*)(pW + (size_t)(i*32)*K + k0);
        }

        __syncthreads();

        #pragma unroll
        for (int ks = 0; ks < BKT; ks += 16) {
            wmma::fragment<wmma::matrix_a, 16, 16, 16, __half, wmma::row_major> af[2];
            wmma::fragment<wmma::matrix_b, 16, 16, 16, __half, wmma::col_major> bf[2];
            #pragma unroll
            for (int i = 0; i < 2; i++)
                wmma::load_matrix_sync(af[i], As + (wm + i*16)*LDA + ks, LDA);
            #pragma unroll
            for (int j = 0; j < 2; j++)
                wmma::load_matrix_sync(bf[j], Ws + (wn + j*16)*LDA + ks, LDA);
            #pragma unroll
            for (int i = 0; i < 2; i++)
                #pragma unroll
                for (int j = 0; j < 2; j++)
                    wmma::mma_sync(acc[i][j], af[i], bf[j], acc[i][j]);
        }
    }

    if (bias == nullptr && oh == nullptr) {
        float* Cp = C + (size_t)blockIdx.z*M*N;
        #pragma unroll
        for (int i = 0; i < 2; i++)
            #pragma unroll
            for (int j = 0; j < 2; j++)
                wmma::store_matrix_sync(Cp + (size_t)(m0+wm+i*16)*N + n0+wn+j*16,
                                        acc[i][j], N, wmma::mem_row_major);
        return;
    }

    __syncthreads();
    float* Ct = (float*)smem;
    #pragma unroll
    for (int i = 0; i < 2; i++)
        #pragma unroll
        for (int j = 0; j < 2; j++)
            wmma::store_matrix_sync(Ct + (wm+i*16)*LDC + wn+j*16,
                                    acc[i][j], LDC, wmma::mem_row_major);
    __syncthreads();

    int col = (tid & 15) * 4;
    int r0  = tid >> 4;
    float4 bv = *(const float4*)(bias + n0 + col);
    #pragma unroll
    for (int rr = 0; rr < 8; rr++) {
        int row = rr*16 + r0;
        float vr[4];
        *(float4*)vr = *(const float4*)&Ct[row*LDC + col];
        vr[0] += bv.x; vr[1] += bv.y; vr[2] += bv.z; vr[3] += bv.w;
        if (act == 1) {
            #pragma unroll
            for (int j = 0; j < 4; j++)
                vr[j] = 0.5f * vr[j] * (1.0f + erff(vr[j] * 0.7071067811865475f));
        }
        size_t base = (size_t)(m0+row)*N + n0 + col;
        if (oh) {
            __half2 p0 = __halves2half2(__float2half_rn(vr[0]), __float2half_rn(vr[1]));
            __half2 p1 = __halves2half2(__float2half_rn(vr[2]), __float2half_rn(vr[3]));
            *(__half2*)&oh[base]   = p0;
            *(__half2*)&oh[base+2] = p1;
        } else {
            *(float4*)(C + base) = *(float4*)vr;
        }
    }
}

// ---------------- fused attention (full; layers 0..13) ----------------
__global__ __launch_bounds__(256) void attn_kernel(const float* __restrict__ qkv,
                                                   const float* __restrict__ qb,
                                                   const float* __restrict__ pr,
                                                   const float* __restrict__ ppw,
                                                   const float* __restrict__ ppb,
                                                   __half* __restrict__ out) {
    int b = blockIdx.x >> 6;
    int h = blockIdx.x & 63;
    __shared__ float Ks[Nc*9];
    __shared__ float Vs[Nc*9];
    int tid = threadIdx.x;
    float4 bq0 = *(const float4*)(qb + h*HDc);
    float4 bq1 = *(const float4*)(qb + h*HDc + 4);
    float4 bk0 = *(const float4*)(qb + Dc + h*HDc);
    float4 bk1 = *(const float4*)(qb + Dc + h*HDc + 4);
    float4 bv0 = *(const float4*)(qb + 2*Dc + h*HDc);
    float4 bv1 = *(const float4*)(qb + 2*Dc + h*HDc + 4);
    {
        int n = tid;
        const float* kp = qkv + (((b*Nc + n)*3 + 1))*Dc + h*HDc;
        const float* vp = kp + Dc;
        float4 k0 = *(const float4*)kp,     k1 = *(const float4*)(kp+4);
        float4 v0 = *(const float4*)vp,     v1 = *(const float4*)(vp+4);
        float* kd = &Ks[n*9];
        kd[0]=k0.x+bk0.x; kd[1]=k0.y+bk0.y; kd[2]=k0.z+bk0.z; kd[3]=k0.w+bk0.w;
        kd[4]=k1.x+bk1.x; kd[5]=k1.y+bk1.y; kd[6]=k1.z+bk1.z; kd[7]=k1.w+bk1.w;
        float* vd = &Vs[n*9];
        vd[0]=v0.x+bv0.x; vd[1]=v0.y+bv0.y; vd[2]=v0.z+bv0.z; vd[3]=v0.w+bv0.w;
        vd[4]=v1.x+bv1.x; vd[5]=v1.y+bv1.y; vd[6]=v1.z+bv1.z; vd[7]=v1.w+bv1.w;
    }
    __syncthreads();
    const float scale = 0.3535533905932738f;
    float pw = ppw[h], pb = ppb[h];
    int warp = tid >> 5, lane = tid & 31;
    #pragma unroll
    for (int r = 0; r < 8; r++) {
        int i = blockIdx.y*64 + warp*8 + r;
        const float* qp = qkv + ((b*Nc + i)*3)*Dc + h*HDc;
        float4 q0 = *(const float4*)qp, q1 = *(const float4*)(qp+4);
        float qr[8];
        qr[0]=q0.x+bq0.x; qr[1]=q0.y+bq0.y; qr[2]=q0.z+bq0.z; qr[3]=q0.w+bq0.w;
        qr[4]=q1.x+bq1.x; qr[5]=q1.y+bq1.y; qr[6]=q1.z+bq1.z; qr[7]=q1.w+bq1.w;
        const float* prow = pr + (b*Nc + i)*Nc;
        float s[8];
        float mx = -1e30f;
        #pragma unroll
        for (int jj = 0; jj < 8; jj++) {
            int j = lane + 32*jj;
            const float* kk = &Ks[j*9];
            float d = qr[0]*kk[0] + qr[1]*kk[1] + qr[2]*kk[2] + qr[3]*kk[3]
                    + qr[4]*kk[4] + qr[5]*kk[5] + qr[6]*kk[6] + qr[7]*kk[7];
            s[jj] = d*scale + prow[j]*pw + pb;
            mx = fmaxf(mx, s[jj]);
        }
        #pragma unroll
        for (int off = 16; off; off >>= 1)
            mx = fmaxf(mx, __shfl_xor_sync(0xffffffff, mx, off));
        float sum = 0.f;
        #pragma unroll
        for (int jj = 0; jj < 8; jj++) { s[jj] = __expf(s[jj]-mx); sum += s[jj]; }
        #pragma unroll
        for (int off = 16; off; off >>= 1)
            sum += __shfl_xor_sync(0xffffffff, sum, off);
        float inv = 1.0f / sum;
        float acc[8] = {};
        #pragma unroll
        for (int jj = 0; jj < 8; jj++) {
            int j = lane + 32*jj;
            float p = s[jj]*inv;
            const float* vv = &Vs[j*9];
            #pragma unroll
            for (int d = 0; d < 8; d++) acc[d] += p*vv[d];
        }
        #pragma unroll
        for (int off = 16; off; off >>= 1) {
            #pragma unroll
            for (int d = 0; d < 8; d++)
                acc[d] += __shfl_xor_sync(0xffffffff, acc[d], off);
        }
        if (lane == 0) {
            __half* op = out + (size_t)(b*Nc + i)*Dc + h*HDc;
            #pragma unroll
            for (int d = 0; d < 8; d++) op[d] = __float2half_rn(acc[d]);
        }
    }
}

// ---------------- attention for query row 0 only (final layer) ----------------
__global__ __launch_bounds__(256) void attn1_kernel(const float* __restrict__ qkv,
                                                    const float* __restrict__ qb,
                                                    const float* __restrict__ pr,
                                                    const float* __restrict__ ppw,
                                                    const float* __restrict__ ppb,
                                                    __half* __restrict__ out) {
    int b = blockIdx.x >> 6;
    int h = blockIdx.x & 63;
    __shared__ float Ks[Nc*9];
    __shared__ float Vs[Nc*9];
    int tid = threadIdx.x;
    float4 bk0 = *(const float4*)(qb + Dc + h*HDc);
    float4 bk1 = *(const float4*)(qb + Dc + h*HDc + 4);
    float4 bv0 = *(const float4*)(qb + 2*Dc + h*HDc);
    float4 bv1 = *(const float4*)(qb + 2*Dc + h*HDc + 4);
    {
        int n = tid;
        const float* kp = qkv + (((b*Nc + n)*3 + 1))*Dc + h*HDc;
        const float* vp = kp + Dc;
        float4 k0 = *(const float4*)kp,     k1 = *(const float4*)(kp+4);
        float4 v0 = *(const float4*)vp,     v1 = *(const float4*)(vp+4);
        float* kd = &Ks[n*9];
        kd[0]=k0.x+bk0.x; kd[1]=k0.y+bk0.y; kd[2]=k0.z+bk0.z; kd[3]=k0.w+bk0.w;
        kd[4]=k1.x+bk1.x; kd[5]=k1.y+bk1.y; kd[6]=k1.z+bk1.z; kd[7]=k1.w+bk1.w;
        float* vd = &Vs[n*9];
        vd[0]=v0.x+bv0.x; vd[1]=v0.y+bv0.y; vd[2]=v0.z+bv0.z; vd[3]=v0.w+bv0.w;
        vd[4]=v1.x+bv1.x; vd[5]=v1.y+bv1.y; vd[6]=v1.z+bv1.z; vd[7]=v1.w+bv1.w;
    }
    __syncthreads();
    if (tid >= 32) return;
    int lane = tid;
    const float scale = 0.3535533905932738f;
    float pw = ppw[h], pb = ppb[h];
    float4 bq0 = *(const float4*)(qb + h*HDc);
    float4 bq1 = *(const float4*)(qb + h*HDc + 4);
    const float* qp = qkv + ((size_t)(b*Nc))*3*Dc + h*HDc;
    float4 q0 = *(const float4*)qp, q1 = *(const float4*)(qp+4);
    float qr[8];
    qr[0]=q0.x+bq0.x; qr[1]=q0.y+bq0.y; qr[2]=q0.z+bq0.z; qr[3]=q0.w+bq0.w;
    qr[4]=q1.x+bq1.x; qr[5]=q1.y+bq1.y; qr[6]=q1.z+bq1.z; qr[7]=q1.w+bq1.w;
    const float* prow = pr + (size_t)(b*Nc)*Nc;
    float s[8];
    float mx = -1e30f;
    #pragma unroll
    for (int jj = 0; jj < 8; jj++) {
        int j = lane + 32*jj;
        const float* kk = &Ks[j*9];
        float d = qr[0]*kk[0] + qr[1]*kk[1] + qr[2]*kk[2] + qr[3]*kk[3]
                + qr[4]*kk[4] + qr[5]*kk[5] + qr[6]*kk[6] + qr[7]*kk[7];
        s[jj] = d*scale + prow[j]*pw + pb;
        mx = fmaxf(mx, s[jj]);
    }
    #pragma unroll
    for (int off = 16; off; off >>= 1)
        mx = fmaxf(mx, __shfl_xor_sync(0xffffffff, mx, off));
    float sum = 0.f;
    #pragma unroll
    for (int jj = 0; jj < 8; jj++) { s[jj] = __expf(s[jj]-mx); sum += s[jj]; }
    #pragma unroll
    for (int off = 16; off; off >>= 1)
        sum += __shfl_xor_sync(0xffffffff, sum, off);
    float inv = 1.0f / sum;
    float acc[8] = {};
    #pragma unroll
    for (int jj = 0; jj < 8; jj++) {
        int j = lane + 32*jj;
        float p = s[jj]*inv;
        const float* vv = &Vs[j*9];
        #pragma unroll
        for (int d = 0; d < 8; d++) acc[d] += p*vv[d];
    }
    #pragma unroll
    for (int off = 16; off; off >>= 1) {
        #pragma unroll
        for (int d = 0; d < 8; d++)
            acc[d] += __shfl_xor_sync(0xffffffff, acc[d], off);
    }
    if (lane == 0) {
        __half* op = out + (size_t)(b*Nc)*Dc + h*HDc;
        #pragma unroll
        for (int d = 0; d < 8; d++) op[d] = __float2half_rn(acc[d]);
    }
}

// ---------------- final tail 1: cls out-proj + residual + LN2 ----------------
// grid Bc, 512 threads. h_row += outproj + ob (+ b2 pre-added for energy).
__global__ __launch_bounds__(512) void tail1_kernel(
    const __half* __restrict__ a16, const __half* __restrict__ owh,
    const float* __restrict__ ob, const float* __restrict__ b2,
    float* __restrict__ h, const float* __restrict__ l2g,
    const float* __restrict__ l2b, __half* __restrict__ x16) {
    __shared__ float arow[Dc];
    __shared__ float outv[Dc];
    __shared__ float rs[16], rs2[16];
    int b = blockIdx.x;
    size_t base = (size_t)(b*Nc)*Dc;
    int tid = threadIdx.x;
    int warp = tid >> 5, lane = tid & 31;
    arow[tid] = __half2float(a16[base + tid]);
    __syncthreads();
    // warp-per-output GEMV: out[d] = arow . owh[d,:]
    for (int d = warp; d < Dc; d += 16) {
        const __half* wr = owh + (size_t)d*Dc;
        float s = 0.f;
        #pragma unroll
        for (int it = 0; it < 2; it++) {
            int k = it*256 + lane*8;
            uint4 u = *(const uint4*)(wr + k);
            const __half2* hp = (const __half2*)&u;
            #pragma unroll
            for (int q = 0; q < 4; q++) {
                float2 f = __half22float2(hp[q]);
                s += arow[k + q*2]*f.x + arow[k + q*2 + 1]*f.y;
            }
        }
        #pragma unroll
        for (int off = 16; off; off >>= 1)
            s += __shfl_xor_sync(0xffffffff, s, off);
        if (lane == 0) outv[d] = s + ob[d];
    }
    __syncthreads();
    // residual + LN over 512
    float val = h[base + tid] + outv[tid];
    float s = val, s2 = val*val;
    #pragma unroll
    for (int off = 16; off; off >>= 1) {
        s  += __shfl_xor_sync(0xffffffff, s,  off);
        s2 += __shfl_xor_sync(0xffffffff, s2, off);
    }
    if (lane == 0) { rs[warp] = s; rs2[warp] = s2; }
    __syncthreads();
    float ts = 0.f, ts2 = 0.f;
    #pragma unroll
    for (int w = 0; w < 16; w++) { ts += rs[w]; ts2 += rs2[w]; }
    float mean = ts * (1.0f/Dc);
    float var  = ts2 * (1.0f/Dc) - mean*mean;
    float rstd = rsqrtf(var + 1e-5f);
    x16[base + tid] = __float2half_rn((val - mean)*rstd*l2g[tid] + l2b[tid]);
    h[base + tid] = val + b2[tid];   // pre-add ffn2 bias for energy
}

// ---------------- final tail 2: cls FFN partials ----------------
// grid (Bc, 8), 256 threads. part[(b*8+c)*Dc + d] = sum_{j in chunk} gelu(x.w1[j]+b1[j]) * w2[d][j]
__global__ __launch_bounds__(256) void tail2_kernel(
    const __half* __restrict__ x16, const __half* __restrict__ w1h,
    const float* __restrict__ b1, const __half* __restrict__ w2h,
    float* __restrict__ part) {
    __shared__ float xr[Dc];
    __shared__ float gv[256];
    int b = blockIdx.x, c = blockIdx.y;
    size_t base = (size_t)(b*Nc)*Dc;
    int tid = threadIdx.x;
    int warp = tid >> 5, lane = tid & 31;
    xr[tid]       = __half2float(x16[base + tid]);
    xr[tid + 256] = __half2float(x16[base + tid + 256]);
    __syncthreads();
    // warp-per-hidden-unit GEMV + gelu
    for (int u = warp; u < 256; u += 8) {
        int j = c*256 + u;
        const __half* wr = w1h + (size_t)j*Dc;
        float s = 0.f;
        #pragma unroll
        for (int it = 0; it < 2; it++) {
            int k = it*256 + lane*8;
            uint4 uu = *(const uint4*)(wr + k);
            const __half2* hp = (const __half2*)&uu;
            #pragma unroll
            for (int q = 0; q < 4; q++) {
                float2 f = __half22float2(hp[q]);
                s += xr[k + q*2]*f.x + xr[k + q*2 + 1]*f.y;
            }
        }
        #pragma unroll
        for (int off = 16; off; off >>= 1)
            s += __shfl_xor_sync(0xffffffff, s, off);
        if (lane == 0) {
            float v = s + b1[j];
            gv[u] = 0.5f * v * (1.0f + erff(v * 0.7071067811865475f));
        }
    }
    __syncthreads();
    // warp-per-d over this 256-chunk of w2
    for (int d = warp; d < Dc; d += 8) {
        const __half* wr = w2h + (size_t)d*Fc + c*256;
        int k = lane*8;
        uint4 uu = *(const uint4*)(wr + k);
        const __half2* hp = (const __half2*)&uu;
        float s = 0.f;
        #pragma unroll
        for (int q = 0; q < 4; q++) {
            float2 f = __half22float2(hp[q]);
            s += gv[k + q*2]*f.x + gv[k + q*2 + 1]*f.y;
        }
        #pragma unroll
        for (int off = 16; off; off >>= 1)
            s += __shfl_xor_sync(0xffffffff, s, off);
        if (lane == 0) part[(size_t)(b*8 + c)*Dc + d] = s;
    }
}

// ---------------- energy head (h row + 8 partials) ----------------
__global__ __launch_bounds__(128) void energy2_kernel(const float* __restrict__ h,
                                                      const float* __restrict__ part,
                                                      const float* __restrict__ enw,
                                                      const float* __restrict__ enb,
                                                      float* __restrict__ out) {
    int b = blockIdx.x;
    int tid = threadIdx.x;
    size_t base = (size_t)(b*Nc)*Dc;
    float s = 0.f;
    #pragma unroll
    for (int j = 0; j < 4; j++) {
        int d = tid + 128*j;
        float v = h[base + d];
        #pragma unroll
        for (int c = 0; c < 8; c++)
            v += part[(size_t)(b*8 + c)*Dc + d];
        s += v*enw[d];
    }
    #pragma unroll
    for (int off = 16; off; off >>= 1)
        s += __shfl_xor_sync(0xffffffff, s, off);
    __shared__ float rs[4];
    int wid = tid >> 5, lane = tid & 31;
    if (lane == 0) rs[wid] = s;
    __syncthreads();
    if (tid == 0)
        out[Bc*Nc*3 + b] = rs[0]+rs[1]+rs[2]+rs[3] + enb[0];
}

// ---------------- SE(3) coordinate update ----------------
__global__ __launch_bounds__(128) void coords_kernel(const float* __restrict__ coords,
                                                     const float* __restrict__ pr,
                                                     const float* __restrict__ uw,
                                                     const float* __restrict__ ub,
                                                     const float* __restrict__ ww,
                                                     const float* __restrict__ wb,
                                                     float* __restrict__ out) {
    int gw = blockIdx.x * 4 + (threadIdx.x >> 5);
    int lane = threadIdx.x & 31;
    int b = gw >> 8, i = gw & 255;
    float u0 = uw[0], u1 = ub[0], w0 = ww[0], w1 = wb[0];
    const float* ci = coords + (b*Nc + i)*3;
    float cx = ci[0], cy = ci[1], cz = ci[2];
    float ax = 0.f, ay = 0.f, az = 0.f;
    const float* prow = pr + (b*Nc + i)*Nc;
    #pragma unroll
    for (int jj = 0; jj < 8; jj++) {
        int j = lane + 32*jj;
        const float* cj = coords + (b*Nc + j)*3;
        float c = (fmaxf(prow[j], 0.f)*u0 + u1)*w0 + w1;
        ax += (cx - cj[0])*c;
        ay += (cy - cj[1])*c;
        az += (cz - cj[2])*c;
    }
    #pragma unroll
    for (int off = 16; off; off >>= 1) {
        ax += __shfl_xor_sync(0xffffffff, ax, off);
        ay += __shfl_xor_sync(0xffffffff, ay, off);
        az += __shfl_xor_sync(0xffffffff, az, off);
    }
    if (lane == 0) {
        float invn = 1.0f / (256.0f + 1e-6f);
        float* op = out + (b*Nc + i)*3;
        op[0] = cx + ax*invn;
        op[1] = cy + ay*invn;
        op[2] = cz + az*invn;
    }
}

// ---------------- host ----------------
extern "C" void kernel_launch(void* const* d_in, const int* in_sizes, int n_in,
                              void* d_out, int out_size) {
    bool has_mask = (n_in >= 31);
    auto IN = [&](int i) -> const void* {
        int k = i;
        if (!has_mask && i > 3) k = i - 1;
        return d_in[k];
    };
    const int*   atom_types = (const int*)  IN(0);
    const float* coords     = (const float*)IN(1);
    const int*   pair_types = (const int*)  IN(2);
    const float* atom_emb   = (const float*)IN(4);
    const float* gmu        = (const float*)IN(5);
    const float* gsigma     = (const float*)IN(6);
    const float* pair_a     = (const float*)IN(7);
    const float* pair_b     = (const float*)IN(8);
    const float* pl_w       = (const float*)IN(9);
    const float* pl_b       = (const float*)IN(10);
    const float* ln1_g      = (const float*)IN(11);
    const float* ln1_b      = (const float*)IN(12);
    const float* qkv_w      = (const float*)IN(13);
    const float* qkv_b      = (const float*)IN(14);
    const float* pp_w       = (const float*)IN(15);
    const float* pp_b       = (const float*)IN(16);
    const float* out_w      = (const float*)IN(17);
    const float* out_b      = (const float*)IN(18);
    const float* ln2_g      = (const float*)IN(19);
    const float* ln2_b      = (const float*)IN(20);
    const float* ffn_w1     = (const float*)IN(21);
    const float* ffn_b1     = (const float*)IN(22);
    const float* ffn_w2     = (const float*)IN(23);
    const float* ffn_b2     = (const float*)IN(24);
    const float* se3_uw     = (const float*)IN(25);
    const float* se3_ub     = (const float*)IN(26);
    const float* se3_ww     = (const float*)IN(27);
    const float* se3_wb     = (const float*)IN(28);
    const float* en_w       = (const float*)IN(29);
    const float* en_b       = (const float*)IN(30);
    float* out = (float*)d_out;

    float *hb, *qkvb, *pairb, *splitb;
    __half *x16, *a16, *f16, *wh;
    cudaGetSymbolAddress((void**)&hb,     g_h);
    cudaGetSymbolAddress((void**)&qkvb,   g_qkv);
    cudaGetSymbolAddress((void**)&pairb,  g_pair);
    cudaGetSymbolAddress((void**)&splitb, g_split);
    cudaGetSymbolAddress((void**)&x16, g_x16);
    cudaGetSymbolAddress((void**)&a16, g_a16);
    cudaGetSymbolAddress((void**)&f16, g_f16);
    cudaGetSymbolAddress((void**)&wh,  g_wh);

    cudaFuncSetAttribute(gemm_fp16_kernel,
                         cudaFuncAttributeMaxDynamicSharedMemorySize, SMEM_DYN);

    // convert all weights to fp16 (once per call)
    wconv_kernel<<<(11796480/4 + 255)/256, 256>>>(qkv_w,  wh + QKVB, 11796480/4);
    wconv_kernel<<<( 3932160/4 + 255)/256, 256>>>(out_w,  wh + OUTB,  3932160/4);
    wconv_kernel<<<(15728640/4 + 255)/256, 256>>>(ffn_w1, wh + F1B,  15728640/4);
    wconv_kernel<<<(15728640/4 + 255)/256, 256>>>(ffn_w2, wh + F2B,  15728640/4);

    tab_kernel<<<(TABN + 256)/256, 256>>>(gmu, gsigma, pl_w, pl_b);
    emb_kernel<<<(Mc*Dc + 255)/256, 256>>>(atom_types, atom_emb, hb);
    pair_kernel<<<(Bc*Nc*Nc)/256, 256>>>(coords, pair_types, pair_a, pair_b, pairb);

    for (int l = 0; l < Lc - 1; l++) {
        const float* qb  = qkv_b + l*3*Dc;
        const float* pwp = pp_w + l*Hc;
        const float* pbp = pp_b + l*Hc;
        const float* ob  = out_b + l*Dc;
        const float* l2g = ln2_g + l*Dc;
        const float* l2b = ln2_b + l*Dc;
        const float* b1  = ffn_b1 + l*Fc;
        const float* b2  = ffn_b2 + l*Dc;
        const __half* qw = wh + QKVB + (size_t)l*786432;
        const __half* ow = wh + OUTB + (size_t)l*262144;
        const __half* w1 = wh + F1B  + (size_t)l*1048576;
        const __half* w2 = wh + F2B  + (size_t)l*1048576;

        if (l == 0)
            ln_kernel<<<Mc/8, 256>>>(hb, ln1_g, ln1_b, x16);
        gemm_fp16_kernel<<<dim3((3*Dc)/BN, Mc/BM, 1), 256, SMEM_DYN>>>(
            x16, qw, nullptr, qkvb, nullptr, Mc, 3*Dc, Dc, 0);
        attn_kernel<<<dim3(Bc*Hc, 4), 256>>>(qkvb, qb, pairb, pwp, pbp, a16);
        gemm_fp16_kernel<<<dim3(Dc/BN, Mc/BM, SPLITK), 256, SMEM_DYN>>>(
            a16, ow, nullptr, splitb, nullptr, Mc, Dc, Dc, 0);
        reduce_ln_kernel<<<Mc/8, 256>>>(splitb, ob, hb, l2g, l2b, x16);
        gemm_fp16_kernel<<<dim3(Fc/BN, Mc/BM, 1), 256, SMEM_DYN>>>(
            x16, w1, b1, nullptr, f16, Mc, Fc, Dc, 1);
        gemm_fp16_kernel<<<dim3(Dc/BN, Mc/BM, SPLITK), 256, SMEM_DYN>>>(
            f16, w2, nullptr, splitb, nullptr, Mc, Dc, Fc, 0);
        reduce_ln_kernel<<<Mc/8, 256>>>(splitb, b2, hb,
                                        ln1_g + (l+1)*Dc, ln1_b + (l+1)*Dc, x16);
    }

    // ---- final layer (l = 14): only cls rows matter after attention ----
    {
        int l = Lc - 1;
        const float* qb  = qkv_b + l*3*Dc;
        const float* pwp = pp_w + l*Hc;
        const float* pbp = pp_b + l*Hc;
        const float* ob  = out_b + l*Dc;
        const float* l2g = ln2_g + l*Dc;
        const float* l2b = ln2_b + l*Dc;
        const float* b1  = ffn_b1 + l*Fc;
        const float* b2  = ffn_b2 + l*Dc;
        const __half* qw = wh + QKVB + (size_t)l*786432;
        const __half* ow = wh + OUTB + (size_t)l*262144;
        const __half* w1 = wh + F1B  + (size_t)l*1048576;
        const __half* w2 = wh + F2B  + (size_t)l*1048576;

        gemm_fp16_kernel<<<dim3((3*Dc)/BN, Mc/BM, 1), 256, SMEM_DYN>>>(
            x16, qw, nullptr, qkvb, nullptr, Mc, 3*Dc, Dc, 0);
        attn1_kernel<<<Bc*Hc, 256>>>(qkvb, qb, pairb, pwp, pbp, a16);
        tail1_kernel<<<Bc, 512>>>(a16, ow, ob, b2, hb, l2g, l2b, x16);
        tail2_kernel<<<dim3(Bc, 8), 256>>>(x16, w1, b1, w2, splitb);
    }

    coords_kernel<<<(Bc*Nc)/4, 128>>>(coords, pairb, se3_uw, se3_ub, se3_ww, se3_wb, out);
    energy2_kernel<<<Bc, 128>>>(hb, splitb, en_w, en_b, out);
    (void)in_sizes; (void)out_size;
}